// round 11
// baseline (speedup 1.0000x reference)
#include <cuda_runtime.h>
#include <cuda_bf16.h>
#include <cstdint>
#include <math.h>

#define N_NODES 50000
#define N_EDGES 800000
#define IN_DIM 128
#define EDGE_DIM 16
#define HIDDEN 128
#define N_LAYERS 3
#define N_GRAPHS 256

typedef unsigned int uint;

// ---------------- scratch (device globals: allocation-free) ----------------
__device__ float g_h[(size_t)N_NODES * HIDDEN];
__device__ float g_agg[(size_t)N_NODES * HIDDEN];
__device__ float g_gi[(size_t)N_NODES * 3 * HIDDEN];
__device__ float g_gh[(size_t)N_NODES * 3 * HIDDEN];
__device__ float g_zsum[N_GRAPHS * HIDDEN];
__device__ unsigned g_zmax[N_GRAPHS * HIDDEN];
__device__ float g_cnt[N_GRAPHS];

// bf16 split weight staging: [K][128] row-major per matrix
#define OFF_LIN 0
#define OFF_M1  16384
#define OFF_M2  71680
#define OFF_WIH 120832
#define OFF_WHH 268288
#define W_TOTAL 415744
__device__ __nv_bfloat16 g_wh[W_TOTAL];
__device__ __nv_bfloat16 g_wl[W_TOTAL];

// ---------------- misc helpers ----------------
__device__ __forceinline__ unsigned fenc(float f) {
    unsigned u = __float_as_uint(f);
    return (u & 0x80000000u) ? ~u : (u | 0x80000000u);
}
__device__ __forceinline__ float fdec(unsigned u) {
    return __uint_as_float((u & 0x80000000u) ? (u ^ 0x80000000u) : ~u);
}

// split two fp32 into packed bf16 hi-word and lo-word (residual)
__device__ __forceinline__ void split2p(float a, float b, uint& h, uint& l) {
    __nv_bfloat162 t = __floats2bfloat162_rn(a, b);
    h = *reinterpret_cast<uint*>(&t);
    float ah = __uint_as_float(h << 16);
    float bh = __uint_as_float(h & 0xffff0000u);
    __nv_bfloat162 t2 = __floats2bfloat162_rn(a - ah, b - bh);
    l = *reinterpret_cast<uint*>(&t2);
}
__device__ __forceinline__ void split_f4(float4 f, uint2& H, uint2& L) {
    split2p(f.x, f.y, H.x, L.x);
    split2p(f.z, f.w, H.y, L.y);
}

// ---------------- mma / ldmatrix primitives (sm_80-level PTX) ----------------
__device__ __forceinline__ uint32_t sm_addr(const void* p) {
    return (uint32_t)__cvta_generic_to_shared(p);
}
__device__ __forceinline__ void ldsm4(uint* r, uint32_t a) {
    asm volatile("ldmatrix.sync.aligned.m8n8.x4.shared.b16 {%0,%1,%2,%3},[%4];"
        : "=r"(r[0]), "=r"(r[1]), "=r"(r[2]), "=r"(r[3]) : "r"(a));
}
__device__ __forceinline__ void ldsm4t(uint* r, uint32_t a) {
    asm volatile("ldmatrix.sync.aligned.m8n8.x4.trans.shared.b16 {%0,%1,%2,%3},[%4];"
        : "=r"(r[0]), "=r"(r[1]), "=r"(r[2]), "=r"(r[3]) : "r"(a));
}
__device__ __forceinline__ void mmabf16(float* d, const uint* a, const uint* b) {
    asm volatile("mma.sync.aligned.m16n8k16.row.col.f32.bf16.bf16.f32 "
        "{%0,%1,%2,%3},{%4,%5,%6,%7},{%8,%9},{%0,%1,%2,%3};"
        : "+f"(d[0]), "+f"(d[1]), "+f"(d[2]), "+f"(d[3])
        : "r"(a[0]), "r"(a[1]), "r"(a[2]), "r"(a[3]), "r"(b[0]), "r"(b[1]));
}

// warp-level GEMM fragment: 2 m16-tiles x NT n8-tiles, NK16 k-steps.
template<int NK16, int NT, int ASTR>
__device__ __forceinline__ void wgemm(float* acc, uint32_t Ab, uint32_t Bb,
                                      uint32_t aOff, uint32_t bOff) {
    #pragma unroll
    for (int k = 0; k < NK16; k++) {
        uint a[2][4];
        ldsm4(a[0], Ab + aOff + k * 32);
        ldsm4(a[1], Ab + aOff + k * 32 + 16 * ASTR);
        uint bb[NT][2];
        #pragma unroll
        for (int p2 = 0; p2 < NT / 2; p2++) {
            uint r[4];
            ldsm4t(r, Bb + bOff + k * 16 * 272 + p2 * 32);
            bb[2*p2][0] = r[0]; bb[2*p2][1] = r[1];
            bb[2*p2+1][0] = r[2]; bb[2*p2+1][1] = r[3];
        }
        #pragma unroll
        for (int mt = 0; mt < 2; mt++)
            #pragma unroll
            for (int nt = 0; nt < NT; nt++)
                mmabf16(acc + (mt * NT + nt) * 4, a[mt], bb[nt]);
    }
}

// ============================================================================
// weight conversion: fp32 -> canonical [K][128] bf16 hi/lo staging
// ============================================================================
__global__ void conv_w_kernel(const float* __restrict__ lin_w,
                              const float* __restrict__ m1,
                              const float* __restrict__ m2,
                              const float* __restrict__ wih,
                              const float* __restrict__ whh)
{
    const int i = blockIdx.x * 256 + threadIdx.x;
    const int seg = blockIdx.y;
    int sz, off; float v;
    switch (seg) {
    case 0: sz = 16384;  off = OFF_LIN; if (i >= sz) return; v = lin_w[i]; break;
    case 1: sz = 55296;  off = OFF_M1;  if (i >= sz) return; v = m1[i]; break;
    case 2: sz = 49152;  off = OFF_M2;  if (i >= sz) return; v = m2[i]; break;
    default: {
        sz = 147456; off = (seg == 3) ? OFF_WIH : OFF_WHH;
        if (i >= sz) return;
        const float* W = (seg == 3) ? wih : whh;
        const int m = i >> 14, t = i & 16383, k = t >> 7, j = t & 127;
        v = W[(m / 3) * 49152 + ((m % 3) * 128 + j) * 128 + k];
        break;
    }}
    __nv_bfloat16 h = __float2bfloat16(v);
    float r = v - __bfloat162float(h);
    g_wh[off + i] = h;
    g_wl[off + i] = __float2bfloat16(r);
}

// ============================================================================
// edge message kernel (mma): 128-edge tiles, 512 thr = 16 warps (warp: 32x32)
// ============================================================================
#define E_AW  304      // A stride bytes (152 bf16)
#define S_W1H 0
#define S_W1L 39168
#define S_W2H 78336
#define S_W2L 113152
#define S_AH  147968
#define S_AL  186880
#define S_B1  225792
#define S_B2  226304
#define S_DST 226816
#define EDGE_SMEM 227328

__global__ __launch_bounds__(512, 1) void edge_mma_kernel(
    const int* __restrict__ src, const int* __restrict__ dst,
    const float* __restrict__ edge_attr, int l,
    const float* __restrict__ b1, const float* __restrict__ b2)
{
    extern __shared__ char sm[];
    const int tid = threadIdx.x;
    const int wid = tid >> 5, lane = tid & 31;
    const uint32_t base = sm_addr(sm);

    // ---- copy split weights to smem (padded stride 136 elems) ----
    {
        const uint* w1h = (const uint*)(g_wh + OFF_M1 + (size_t)l * 18432);
        const uint* w1l = (const uint*)(g_wl + OFF_M1 + (size_t)l * 18432);
        for (int i = tid; i < 144 * 64; i += 512) {
            const int k = i >> 6, n2 = i & 63;
            ((uint*)(sm + S_W1H))[k * 68 + n2] = w1h[i];
            ((uint*)(sm + S_W1L))[k * 68 + n2] = w1l[i];
        }
        const uint* w2h = (const uint*)(g_wh + OFF_M2 + (size_t)l * 16384);
        const uint* w2l = (const uint*)(g_wl + OFF_M2 + (size_t)l * 16384);
        for (int i = tid; i < 128 * 64; i += 512) {
            const int k = i >> 6, n2 = i & 63;
            ((uint*)(sm + S_W2H))[k * 68 + n2] = w2h[i];
            ((uint*)(sm + S_W2L))[k * 68 + n2] = w2l[i];
        }
        if (tid < 128) {
            ((float*)(sm + S_B1))[tid] = b1[tid];
            ((float*)(sm + S_B2))[tid] = b2[tid];
        }
    }
    __syncthreads();

    const float* sb1 = (const float*)(sm + S_B1);
    const float* sb2 = (const float*)(sm + S_B2);
    int* sDst = (int*)(sm + S_DST);
    const int m0 = (wid & 3) * 32, n0 = (wid >> 2) * 32;
    const uint32_t aOff = (uint32_t)(m0 + (lane & 15)) * E_AW + (lane >> 4) * 16;
    const uint32_t bOff = (uint32_t)(lane & 15) * 272 + n0 * 2 + (lane >> 4) * 16;
    const uint32_t aH = base + S_AH, aL = base + S_AL;
    const uint32_t w1H = base + S_W1H, w1L = base + S_W1L;
    const uint32_t w2H = base + S_W2H, w2L = base + S_W2L;

    const int ntiles = N_EDGES / 128;    // 6250
    for (int t = blockIdx.x; t < ntiles; t += gridDim.x) {
        const int e0 = t * 128;
        // ---- gather: h[src] + edge_attr -> bf16 hi/lo tiles (4 thr/row) ----
        {
            const int row = tid >> 2, q = tid & 3;
            const int e = e0 + row;
            if (tid < 128) sDst[tid] = dst[e0 + tid];
            const int s = src[e];
            const float4* hp = (const float4*)(g_h + (size_t)s * 128) + q * 8;
            const uint b0 = (uint)row * E_AW + q * 64;
            #pragma unroll
            for (int i = 0; i < 8; i++) {
                uint2 H, L; split_f4(hp[i], H, L);
                *(uint2*)(sm + S_AH + b0 + i * 8) = H;
                *(uint2*)(sm + S_AL + b0 + i * 8) = L;
            }
            if (q == 0) {
                const float4* ep = (const float4*)(edge_attr + (size_t)e * 16);
                #pragma unroll
                for (int i = 0; i < 4; i++) {
                    uint2 H, L; split_f4(ep[i], H, L);
                    *(uint2*)(sm + S_AH + (uint)row * E_AW + 256 + i * 8) = H;
                    *(uint2*)(sm + S_AL + (uint)row * E_AW + 256 + i * 8) = L;
                }
            }
        }
        __syncthreads();

        // ---- GEMM1 (K=144, 3-pass split) ----
        float acc[8][4];
        #pragma unroll
        for (int i = 0; i < 8; i++) { acc[i][0]=0; acc[i][1]=0; acc[i][2]=0; acc[i][3]=0; }
        #pragma unroll 1
        for (int p = 0; p < 3; p++)
            wgemm<9, 4, E_AW>(&acc[0][0], (p == 2) ? aL : aH,
                              (p == 1) ? w1L : w1H, aOff, bOff);
        __syncthreads();   // all warps done reading A before overwrite

        // ---- epilogue1: relu(+b1) -> re-split into A buffers ----
        #pragma unroll
        for (int mt = 0; mt < 2; mt++)
            #pragma unroll
            for (int nt = 0; nt < 4; nt++) {
                float* a4 = acc[mt * 4 + nt];
                const int col = n0 + nt * 8 + 2 * (lane & 3);
                const int r0 = m0 + mt * 16 + (lane >> 2);
                float v0 = fmaxf(a4[0] + sb1[col], 0.f), v1 = fmaxf(a4[1] + sb1[col+1], 0.f);
                float v2 = fmaxf(a4[2] + sb1[col], 0.f), v3 = fmaxf(a4[3] + sb1[col+1], 0.f);
                uint h, lo;
                split2p(v0, v1, h, lo);
                *(uint*)(sm + S_AH + (uint)r0 * E_AW + col * 2) = h;
                *(uint*)(sm + S_AL + (uint)r0 * E_AW + col * 2) = lo;
                split2p(v2, v3, h, lo);
                *(uint*)(sm + S_AH + (uint)(r0 + 8) * E_AW + col * 2) = h;
                *(uint*)(sm + S_AL + (uint)(r0 + 8) * E_AW + col * 2) = lo;
            }
        __syncthreads();

        // ---- GEMM2 (K=128, 3-pass split) ----
        #pragma unroll
        for (int i = 0; i < 8; i++) { acc[i][0]=0; acc[i][1]=0; acc[i][2]=0; acc[i][3]=0; }
        #pragma unroll 1
        for (int p = 0; p < 3; p++)
            wgemm<8, 4, E_AW>(&acc[0][0], (p == 2) ? aL : aH,
                              (p == 1) ? w2L : w2H, aOff, bOff);

        // ---- epilogue2: +b2, scatter-add ----
        #pragma unroll
        for (int mt = 0; mt < 2; mt++)
            #pragma unroll
            for (int nt = 0; nt < 4; nt++) {
                float* a4 = acc[mt * 4 + nt];
                const int col = n0 + nt * 8 + 2 * (lane & 3);
                const int r0 = m0 + mt * 16 + (lane >> 2);
                const int d0 = sDst[r0], d1 = sDst[r0 + 8];
                atomicAdd(g_agg + (size_t)d0 * 128 + col,     a4[0] + sb2[col]);
                atomicAdd(g_agg + (size_t)d0 * 128 + col + 1, a4[1] + sb2[col + 1]);
                atomicAdd(g_agg + (size_t)d1 * 128 + col,     a4[2] + sb2[col]);
                atomicAdd(g_agg + (size_t)d1 * 128 + col + 1, a4[3] + sb2[col + 1]);
            }
        __syncthreads();   // before next tile's gather overwrites A
    }
}

// ============================================================================
// node GEMM body (mma): out[n,128] = act(A[n,128] @ W + b); 64-row tiles,
// 256 thr = 8 warps (warp 32x32), 2 CTAs/SM.
// ============================================================================
#define N_AW 272                 // A stride bytes (136 bf16)
#define NS_WH 0
#define NS_WL 34816
#define NS_AH 69632
#define NS_AL 87040
#define NS_B  104448
#define NODE_SMEM 104960

__device__ __forceinline__ void node_body(
    const float* __restrict__ A, float* __restrict__ out, int ostride,
    const uint* __restrict__ WhU, const uint* __restrict__ WlU,
    const float* __restrict__ bias, int relu)
{
    extern __shared__ char sm[];
    const int tid = threadIdx.x;
    const int wid = tid >> 5, lane = tid & 31;
    const uint32_t base = sm_addr(sm);

    for (int i = tid; i < 128 * 64; i += 256) {
        const int k = i >> 6, n2 = i & 63;
        ((uint*)(sm + NS_WH))[k * 68 + n2] = WhU[i];
        ((uint*)(sm + NS_WL))[k * 68 + n2] = WlU[i];
    }
    if (tid < 128) ((float*)(sm + NS_B))[tid] = bias[tid];
    __syncthreads();

    const float* sb = (const float*)(sm + NS_B);
    const int m0 = (wid & 1) * 32, n0 = (wid >> 1) * 32;
    const uint32_t aOff = (uint32_t)(m0 + (lane & 15)) * N_AW + (lane >> 4) * 16;
    const uint32_t bOff = (uint32_t)(lane & 15) * 272 + n0 * 2 + (lane >> 4) * 16;
    const uint32_t aH = base + NS_AH, aL = base + NS_AL;
    const uint32_t wH = base + NS_WH, wL = base + NS_WL;

    const int ntiles = (N_NODES + 63) / 64;  // 782
    for (int t = blockIdx.x; t < ntiles; t += gridDim.x) {
        const int r0g = t * 64;
        {   // load + split A rows
            const int trow = tid >> 2, q = tid & 3;
            const int rg = r0g + trow;
            const uint b0 = (uint)trow * N_AW + q * 64;
            if (rg < N_NODES) {
                const float4* hp = (const float4*)(A + (size_t)rg * 128) + q * 8;
                #pragma unroll
                for (int i = 0; i < 8; i++) {
                    uint2 H, L; split_f4(hp[i], H, L);
                    *(uint2*)(sm + NS_AH + b0 + i * 8) = H;
                    *(uint2*)(sm + NS_AL + b0 + i * 8) = L;
                }
            } else {
                const uint2 z = make_uint2(0u, 0u);
                #pragma unroll
                for (int i = 0; i < 8; i++) {
                    *(uint2*)(sm + NS_AH + b0 + i * 8) = z;
                    *(uint2*)(sm + NS_AL + b0 + i * 8) = z;
                }
            }
        }
        __syncthreads();

        float acc[8][4];
        #pragma unroll
        for (int i = 0; i < 8; i++) { acc[i][0]=0; acc[i][1]=0; acc[i][2]=0; acc[i][3]=0; }
        #pragma unroll 1
        for (int p = 0; p < 3; p++)
            wgemm<8, 4, N_AW>(&acc[0][0], (p == 2) ? aL : aH,
                              (p == 1) ? wL : wH, aOff, bOff);
        __syncthreads();

        #pragma unroll
        for (int mt = 0; mt < 2; mt++)
            #pragma unroll
            for (int nt = 0; nt < 4; nt++) {
                float* a4 = acc[mt * 4 + nt];
                const int col = n0 + nt * 8 + 2 * (lane & 3);
                const int r = m0 + mt * 16 + (lane >> 2);
                const int rg0 = r0g + r, rg1 = rg0 + 8;
                float v0 = a4[0] + sb[col], v1 = a4[1] + sb[col + 1];
                float v2 = a4[2] + sb[col], v3 = a4[3] + sb[col + 1];
                if (relu) {
                    v0 = fmaxf(v0, 0.f); v1 = fmaxf(v1, 0.f);
                    v2 = fmaxf(v2, 0.f); v3 = fmaxf(v3, 0.f);
                }
                if (rg0 < N_NODES)
                    *(float2*)(out + (size_t)rg0 * ostride + col) = make_float2(v0, v1);
                if (rg1 < N_NODES)
                    *(float2*)(out + (size_t)rg1 * ostride + col) = make_float2(v2, v3);
            }
    }
}

__global__ __launch_bounds__(256, 2) void lin_mma_kernel(
    const float* __restrict__ x, const float* __restrict__ b)
{
    node_body(x, g_h, 128, (const uint*)(g_wh + OFF_LIN),
              (const uint*)(g_wl + OFF_LIN), b, 1);
}

__global__ __launch_bounds__(256, 2) void gru_mma_kernel(
    int l, const float* __restrict__ bih, const float* __restrict__ bhh)
{
    const int which = blockIdx.y / 3, gate = blockIdx.y % 3;
    const float* A = which ? g_h : g_agg;
    float* out = (which ? g_gh : g_gi) + gate * 128;
    const size_t wOff = (size_t)(which ? OFF_WHH : OFF_WIH) + (size_t)(l * 3 + gate) * 16384;
    const float* bias = (which ? bhh : bih) + gate * 128;
    node_body(A, out, 384, (const uint*)(g_wh + wOff), (const uint*)(g_wl + wOff), bias, 0);
}

// ============================================================================
// fused GRU gates + BatchNorm + residual
// ============================================================================
__global__ void gru_gate_kernel(
    const float* __restrict__ gamma, const float* __restrict__ beta,
    const float* __restrict__ mean, const float* __restrict__ var)
{
    const int idx = blockIdx.x * blockDim.x + threadIdx.x;
    if (idx >= N_NODES * HIDDEN) return;
    const int c = idx & 127;
    const size_t n = (size_t)(idx >> 7);
    const float* gi = g_gi + n * 384;
    const float* gh = g_gh + n * 384;
    const float hv = g_h[idx];
    const float r = 1.f / (1.f + expf(-(gi[c] + gh[c])));
    const float z = 1.f / (1.f + expf(-(gi[128 + c] + gh[128 + c])));
    const float nn = tanhf(gi[256 + c] + r * gh[256 + c]);
    const float hnew = (1.f - z) * nn + z * hv;
    const float bn = (hnew - mean[c]) * rsqrtf(var[c] + 1e-5f) * gamma[c] + beta[c];
    g_h[idx] = hv + bn;
}

// ---------------- aux kernels ----------------
__global__ void zero_agg_kernel() {
    const int idx = blockIdx.x * blockDim.x + threadIdx.x;
    if (idx < N_NODES * HIDDEN / 4)
        ((float4*)g_agg)[idx] = make_float4(0.f, 0.f, 0.f, 0.f);
}

__global__ void init_readout_kernel() {
    const int idx = blockIdx.x * blockDim.x + threadIdx.x;
    if (idx < N_GRAPHS * HIDDEN) { g_zsum[idx] = 0.f; g_zmax[idx] = 0x00800000u; }
    if (idx < N_GRAPHS) g_cnt[idx] = 0.f;
}

__global__ void seg_reduce_kernel(const int* __restrict__ batch) {
    const int gid = blockIdx.x * blockDim.x + threadIdx.x;
    if (gid >= N_NODES * 32) return;
    const int n = gid >> 5, q = gid & 31;
    const int g = batch[n];
    const float4 hv = *(const float4*)(g_h + (size_t)n * 128 + q * 4);
    float* zs = g_zsum + g * 128 + q * 4;
    atomicAdd(zs + 0, hv.x); atomicAdd(zs + 1, hv.y);
    atomicAdd(zs + 2, hv.z); atomicAdd(zs + 3, hv.w);
    unsigned* zm = g_zmax + g * 128 + q * 4;
    atomicMax(zm + 0, fenc(hv.x)); atomicMax(zm + 1, fenc(hv.y));
    atomicMax(zm + 2, fenc(hv.z)); atomicMax(zm + 3, fenc(hv.w));
    if (q == 0) atomicAdd(g_cnt + g, 1.f);
}

__global__ void readout_kernel(const float* __restrict__ ro_w,
                               const float* __restrict__ ro_b,
                               float* __restrict__ out)
{
    __shared__ float sbuf[256];
    const int g = blockIdx.x, j = threadIdx.x;
    const float c = g_cnt[g];
    const float inv = 1.f / fmaxf(c, 1.f);
    sbuf[j]       = g_zsum[g * 128 + j] * inv;
    sbuf[128 + j] = (c > 0.f) ? fdec(g_zmax[g * 128 + j]) : 0.f;
    __syncthreads();
    float acc = ro_b[j];
    #pragma unroll 8
    for (int k = 0; k < 256; k++) acc = fmaf(sbuf[k], ro_w[k * 128 + j], acc);
    out[g * 128 + j] = fmaxf(acc, 0.f);
}

// ============================================================================
extern "C" void kernel_launch(void* const* d_in, const int* in_sizes, int n_in,
                              void* d_out, int out_size)
{
    const int shift = (in_sizes[4] == 1) ? 1 : 0;
    const float* x         = (const float*)d_in[0];
    const int*   edge_idx  = (const int*)  d_in[1];
    const float* edge_attr = (const float*)d_in[2];
    const int*   batch     = (const int*)  d_in[3];
    const float* lin_in_w  = (const float*)d_in[4 + shift];
    const float* lin_in_b  = (const float*)d_in[5 + shift];
    const float* msg_w1    = (const float*)d_in[6 + shift];
    const float* msg_b1    = (const float*)d_in[7 + shift];
    const float* msg_w2    = (const float*)d_in[8 + shift];
    const float* msg_b2    = (const float*)d_in[9 + shift];
    const float* bn_gamma  = (const float*)d_in[10 + shift];
    const float* bn_beta   = (const float*)d_in[11 + shift];
    const float* bn_mean   = (const float*)d_in[12 + shift];
    const float* bn_var    = (const float*)d_in[13 + shift];
    const float* gru_wih   = (const float*)d_in[14 + shift];
    const float* gru_whh   = (const float*)d_in[15 + shift];
    const float* gru_bih   = (const float*)d_in[16 + shift];
    const float* gru_bhh   = (const float*)d_in[17 + shift];
    const float* ro_w      = (const float*)d_in[18 + shift];
    const float* ro_b      = (const float*)d_in[19 + shift];
    float* out = (float*)d_out;

    static bool inited = false;
    if (!inited) {
        cudaFuncSetAttribute(edge_mma_kernel, cudaFuncAttributeMaxDynamicSharedMemorySize, EDGE_SMEM);
        cudaFuncSetAttribute(lin_mma_kernel,  cudaFuncAttributeMaxDynamicSharedMemorySize, NODE_SMEM);
        cudaFuncSetAttribute(gru_mma_kernel,  cudaFuncAttributeMaxDynamicSharedMemorySize, NODE_SMEM);
        inited = true;
    }

    const int* src = edge_idx;
    const int* dst = edge_idx + N_EDGES;

    conv_w_kernel<<<dim3(576, 5), 256>>>(lin_in_w, msg_w1, msg_w2, gru_wih, gru_whh);
    lin_mma_kernel<<<296, 256, NODE_SMEM>>>(x, lin_in_b);

    for (int l = 0; l < N_LAYERS; l++) {
        zero_agg_kernel<<<(N_NODES * HIDDEN / 4 + 255) / 256, 256>>>();
        edge_mma_kernel<<<148, 512, EDGE_SMEM>>>(
            src, dst, edge_attr, l, msg_b1 + l * 128, msg_b2 + l * 128);
        gru_mma_kernel<<<dim3(296, 6), 256, NODE_SMEM>>>(
            l, gru_bih + (size_t)l * 384, gru_bhh + (size_t)l * 384);
        gru_gate_kernel<<<(N_NODES * HIDDEN + 255) / 256, 256>>>(
            bn_gamma + l * 128, bn_beta + l * 128, bn_mean + l * 128, bn_var + l * 128);
    }

    init_readout_kernel<<<(N_GRAPHS * HIDDEN + 255) / 256, 256>>>();
    seg_reduce_kernel<<<(N_NODES * 32 + 255) / 256, 256>>>(batch);
    readout_kernel<<<N_GRAPHS, 128>>>(ro_w, ro_b, out);
}

// round 12
// speedup vs baseline: 1.0378x; 1.0378x over previous
#include <cuda_runtime.h>
#include <cuda_bf16.h>
#include <cstdint>
#include <math.h>

#define N_NODES 50000
#define N_EDGES 800000
#define IN_DIM 128
#define EDGE_DIM 16
#define HIDDEN 128
#define N_LAYERS 3
#define N_GRAPHS 256

typedef unsigned int uint;

// ---------------- scratch (device globals: allocation-free) ----------------
__device__ float g_h[(size_t)N_NODES * HIDDEN];
__device__ float g_agg[(size_t)N_NODES * HIDDEN];
__device__ float g_gi[(size_t)N_NODES * 3 * HIDDEN];
__device__ float g_gh[(size_t)N_NODES * 3 * HIDDEN];
__device__ float g_zsum[N_GRAPHS * HIDDEN];
__device__ unsigned g_zmax[N_GRAPHS * HIDDEN];
__device__ float g_cnt[N_GRAPHS];

// bf16 split weight staging: [K][128] row-major per matrix
#define OFF_LIN 0
#define OFF_M1  16384
#define OFF_M2  71680
#define OFF_WIH 120832
#define OFF_WHH 268288
#define W_TOTAL 415744
__device__ __nv_bfloat16 g_wh[W_TOTAL];
__device__ __nv_bfloat16 g_wl[W_TOTAL];

// ---------------- misc helpers ----------------
__device__ __forceinline__ unsigned fenc(float f) {
    unsigned u = __float_as_uint(f);
    return (u & 0x80000000u) ? ~u : (u | 0x80000000u);
}
__device__ __forceinline__ float fdec(unsigned u) {
    return __uint_as_float((u & 0x80000000u) ? (u ^ 0x80000000u) : ~u);
}
__device__ __forceinline__ void red_add_v4(float* p, float a, float b, float c, float d) {
    asm volatile("red.global.add.v4.f32 [%0],{%1,%2,%3,%4};"
                 :: "l"(p), "f"(a), "f"(b), "f"(c), "f"(d) : "memory");
}

// split two fp32 into packed bf16 hi-word and lo-word (residual)
__device__ __forceinline__ void split2p(float a, float b, uint& h, uint& l) {
    __nv_bfloat162 t = __floats2bfloat162_rn(a, b);
    h = *reinterpret_cast<uint*>(&t);
    float ah = __uint_as_float(h << 16);
    float bh = __uint_as_float(h & 0xffff0000u);
    __nv_bfloat162 t2 = __floats2bfloat162_rn(a - ah, b - bh);
    l = *reinterpret_cast<uint*>(&t2);
}
__device__ __forceinline__ void split_f4(float4 f, uint2& H, uint2& L) {
    split2p(f.x, f.y, H.x, L.x);
    split2p(f.z, f.w, H.y, L.y);
}

// ---------------- mma / ldmatrix primitives (sm_80-level PTX) ----------------
__device__ __forceinline__ uint32_t sm_addr(const void* p) {
    return (uint32_t)__cvta_generic_to_shared(p);
}
__device__ __forceinline__ void ldsm4(uint* r, uint32_t a) {
    asm volatile("ldmatrix.sync.aligned.m8n8.x4.shared.b16 {%0,%1,%2,%3},[%4];"
        : "=r"(r[0]), "=r"(r[1]), "=r"(r[2]), "=r"(r[3]) : "r"(a));
}
__device__ __forceinline__ void ldsm4t(uint* r, uint32_t a) {
    asm volatile("ldmatrix.sync.aligned.m8n8.x4.trans.shared.b16 {%0,%1,%2,%3},[%4];"
        : "=r"(r[0]), "=r"(r[1]), "=r"(r[2]), "=r"(r[3]) : "r"(a));
}
__device__ __forceinline__ void mmabf16(float* d, const uint* a, const uint* b) {
    asm volatile("mma.sync.aligned.m16n8k16.row.col.f32.bf16.bf16.f32 "
        "{%0,%1,%2,%3},{%4,%5,%6,%7},{%8,%9},{%0,%1,%2,%3};"
        : "+f"(d[0]), "+f"(d[1]), "+f"(d[2]), "+f"(d[3])
        : "r"(a[0]), "r"(a[1]), "r"(a[2]), "r"(a[3]), "r"(b[0]), "r"(b[1]));
}

// warp-level GEMM fragment: 2 m16-tiles x NT n8-tiles, NK16 k-steps.
template<int NK16, int NT, int ASTR>
__device__ __forceinline__ void wgemm(float* acc, uint32_t Ab, uint32_t Bb,
                                      uint32_t aOff, uint32_t bOff) {
    #pragma unroll
    for (int k = 0; k < NK16; k++) {
        uint a[2][4];
        ldsm4(a[0], Ab + aOff + k * 32);
        ldsm4(a[1], Ab + aOff + k * 32 + 16 * ASTR);
        uint bb[NT][2];
        #pragma unroll
        for (int p2 = 0; p2 < NT / 2; p2++) {
            uint r[4];
            ldsm4t(r, Bb + bOff + k * 16 * 272 + p2 * 32);
            bb[2*p2][0] = r[0]; bb[2*p2][1] = r[1];
            bb[2*p2+1][0] = r[2]; bb[2*p2+1][1] = r[3];
        }
        #pragma unroll
        for (int mt = 0; mt < 2; mt++)
            #pragma unroll
            for (int nt = 0; nt < NT; nt++)
                mmabf16(acc + (mt * NT + nt) * 4, a[mt], bb[nt]);
    }
}

// ============================================================================
// weight conversion: fp32 -> canonical [K][128] bf16 hi/lo staging
// ============================================================================
__global__ void conv_w_kernel(const float* __restrict__ lin_w,
                              const float* __restrict__ m1,
                              const float* __restrict__ m2,
                              const float* __restrict__ wih,
                              const float* __restrict__ whh)
{
    const int i = blockIdx.x * 256 + threadIdx.x;
    const int seg = blockIdx.y;
    int sz, off; float v;
    switch (seg) {
    case 0: sz = 16384;  off = OFF_LIN; if (i >= sz) return; v = lin_w[i]; break;
    case 1: sz = 55296;  off = OFF_M1;  if (i >= sz) return; v = m1[i]; break;
    case 2: sz = 49152;  off = OFF_M2;  if (i >= sz) return; v = m2[i]; break;
    default: {
        sz = 147456; off = (seg == 3) ? OFF_WIH : OFF_WHH;
        if (i >= sz) return;
        const float* W = (seg == 3) ? wih : whh;
        const int m = i >> 14, t = i & 16383, k = t >> 7, j = t & 127;
        v = W[(m / 3) * 49152 + ((m % 3) * 128 + j) * 128 + k];
        break;
    }}
    __nv_bfloat16 h = __float2bfloat16(v);
    float r = v - __bfloat162float(h);
    g_wh[off + i] = h;
    g_wl[off + i] = __float2bfloat16(r);
}

// ============================================================================
// edge message kernel (mma): 128-edge tiles, 256 thr = 8 warps (warp: 32x64)
// scatter via red.global.add.v4.f32 (lane-pair shuffle to form 4 contig cols)
// ============================================================================
#define E_AW  304      // A stride bytes (152 bf16)
#define S_W1H 0
#define S_W1L 39168
#define S_W2H 78336
#define S_W2L 113152
#define S_AH  147968
#define S_AL  186880
#define S_B1  225792
#define S_B2  226304
#define S_DST 226816
#define EDGE_SMEM 227328

__global__ __launch_bounds__(256, 1) void edge_mma_kernel(
    const int* __restrict__ src, const int* __restrict__ dst,
    const float* __restrict__ edge_attr, int l,
    const float* __restrict__ b1, const float* __restrict__ b2)
{
    extern __shared__ char sm[];
    const int tid = threadIdx.x;
    const int wid = tid >> 5, lane = tid & 31;
    const uint32_t base = sm_addr(sm);

    // ---- copy split weights to smem (padded stride 136 elems) ----
    {
        const uint* w1h = (const uint*)(g_wh + OFF_M1 + (size_t)l * 18432);
        const uint* w1l = (const uint*)(g_wl + OFF_M1 + (size_t)l * 18432);
        for (int i = tid; i < 144 * 64; i += 256) {
            const int k = i >> 6, n2 = i & 63;
            ((uint*)(sm + S_W1H))[k * 68 + n2] = w1h[i];
            ((uint*)(sm + S_W1L))[k * 68 + n2] = w1l[i];
        }
        const uint* w2h = (const uint*)(g_wh + OFF_M2 + (size_t)l * 16384);
        const uint* w2l = (const uint*)(g_wl + OFF_M2 + (size_t)l * 16384);
        for (int i = tid; i < 128 * 64; i += 256) {
            const int k = i >> 6, n2 = i & 63;
            ((uint*)(sm + S_W2H))[k * 68 + n2] = w2h[i];
            ((uint*)(sm + S_W2L))[k * 68 + n2] = w2l[i];
        }
        if (tid < 128) {
            ((float*)(sm + S_B1))[tid] = b1[tid];
            ((float*)(sm + S_B2))[tid] = b2[tid];
        }
    }
    __syncthreads();

    const float* sb1 = (const float*)(sm + S_B1);
    const float* sb2 = (const float*)(sm + S_B2);
    int* sDst = (int*)(sm + S_DST);
    const int m0 = (wid & 3) * 32, n0 = (wid >> 2) * 64;
    const uint32_t aOff = (uint32_t)(m0 + (lane & 15)) * E_AW + (lane >> 4) * 16;
    const uint32_t bOff = (uint32_t)(lane & 15) * 272 + n0 * 2 + (lane >> 4) * 16;
    const uint32_t aH = base + S_AH, aL = base + S_AL;
    const uint32_t w1H = base + S_W1H, w1L = base + S_W1L;
    const uint32_t w2H = base + S_W2H, w2L = base + S_W2L;
    const int q = lane & 3, qodd = q & 1;

    const int ntiles = N_EDGES / 128;    // 6250
    for (int t = blockIdx.x; t < ntiles; t += gridDim.x) {
        const int e0 = t * 128;
        // ---- gather: h[src] + edge_attr -> bf16 hi/lo tiles (2 thr/row) ----
        {
            const int row = tid >> 1, half = tid & 1;
            const int e = e0 + row;
            if (tid < 128) sDst[tid] = dst[e0 + tid];
            const int s = src[e];
            const float4* hp = (const float4*)(g_h + (size_t)s * 128) + half * 16;
            const uint b0 = (uint)row * E_AW + half * 128;
            #pragma unroll
            for (int i = 0; i < 16; i++) {
                uint2 H, L; split_f4(hp[i], H, L);
                *(uint2*)(sm + S_AH + b0 + i * 8) = H;
                *(uint2*)(sm + S_AL + b0 + i * 8) = L;
            }
            if (!half) {
                const float4* ep = (const float4*)(edge_attr + (size_t)e * 16);
                #pragma unroll
                for (int i = 0; i < 4; i++) {
                    uint2 H, L; split_f4(ep[i], H, L);
                    *(uint2*)(sm + S_AH + (uint)row * E_AW + 256 + i * 8) = H;
                    *(uint2*)(sm + S_AL + (uint)row * E_AW + 256 + i * 8) = L;
                }
            }
        }
        __syncthreads();

        // ---- GEMM1 (K=144, 3-pass split) ----
        float acc[16][4];
        #pragma unroll
        for (int i = 0; i < 16; i++) { acc[i][0]=0; acc[i][1]=0; acc[i][2]=0; acc[i][3]=0; }
        #pragma unroll 1
        for (int p = 0; p < 3; p++)
            wgemm<9, 8, E_AW>(&acc[0][0], (p == 2) ? aL : aH,
                              (p == 1) ? w1L : w1H, aOff, bOff);
        __syncthreads();   // all warps done reading A before overwrite

        // ---- epilogue1: relu(+b1) -> re-split into A buffers ----
        #pragma unroll
        for (int mt = 0; mt < 2; mt++)
            #pragma unroll
            for (int nt = 0; nt < 8; nt++) {
                float* a4 = acc[mt * 8 + nt];
                const int col = n0 + nt * 8 + 2 * q;
                const int r0 = m0 + mt * 16 + (lane >> 2);
                float v0 = fmaxf(a4[0] + sb1[col], 0.f), v1 = fmaxf(a4[1] + sb1[col+1], 0.f);
                float v2 = fmaxf(a4[2] + sb1[col], 0.f), v3 = fmaxf(a4[3] + sb1[col+1], 0.f);
                uint h, lo;
                split2p(v0, v1, h, lo);
                *(uint*)(sm + S_AH + (uint)r0 * E_AW + col * 2) = h;
                *(uint*)(sm + S_AL + (uint)r0 * E_AW + col * 2) = lo;
                split2p(v2, v3, h, lo);
                *(uint*)(sm + S_AH + (uint)(r0 + 8) * E_AW + col * 2) = h;
                *(uint*)(sm + S_AL + (uint)(r0 + 8) * E_AW + col * 2) = lo;
            }
        __syncthreads();

        // ---- GEMM2 (K=128, 3-pass split) ----
        #pragma unroll
        for (int i = 0; i < 16; i++) { acc[i][0]=0; acc[i][1]=0; acc[i][2]=0; acc[i][3]=0; }
        #pragma unroll 1
        for (int p = 0; p < 3; p++)
            wgemm<8, 8, E_AW>(&acc[0][0], (p == 2) ? aL : aH,
                              (p == 1) ? w2L : w2H, aOff, bOff);

        // ---- epilogue2: +b2, lane-pair shuffle -> one v4 reduction each ----
        #pragma unroll
        for (int mt = 0; mt < 2; mt++)
            #pragma unroll
            for (int nt = 0; nt < 8; nt++) {
                float* a4 = acc[mt * 8 + nt];
                const int col  = n0 + nt * 8 + 2 * q;
                const int colb = n0 + nt * 8 + 2 * (q & ~1);   // 16B-aligned base
                const int r0 = m0 + mt * 16 + (lane >> 2);
                const float v0 = a4[0] + sb2[col], v1 = a4[1] + sb2[col + 1];
                const float v2 = a4[2] + sb2[col], v3 = a4[3] + sb2[col + 1];
                // even lane keeps row r0 (its v0,v1 = cols colb,colb+1);
                // odd lane keeps row r0+8 (its v2,v3 = cols colb+2,colb+3).
                const float s0 = qodd ? v0 : v2;
                const float s1 = qodd ? v1 : v3;
                const float x0 = __shfl_xor_sync(0xffffffffu, s0, 1);
                const float x1 = __shfl_xor_sync(0xffffffffu, s1, 1);
                const int drow = qodd ? sDst[r0 + 8] : sDst[r0];
                float* p = g_agg + (size_t)drow * 128 + colb;
                if (qodd) red_add_v4(p, x0, x1, v2, v3);
                else      red_add_v4(p, v0, v1, x0, x1);
            }
        __syncthreads();   // before next tile's gather overwrites A
    }
}

// ============================================================================
// node GEMM body (mma): out[n,128] = act(A[n,128] @ W + b); 64-row tiles,
// 256 thr = 8 warps (warp 32x32), 2 CTAs/SM.
// ============================================================================
#define N_AW 272                 // A stride bytes (136 bf16)
#define NS_WH 0
#define NS_WL 34816
#define NS_AH 69632
#define NS_AL 87040
#define NS_B  104448
#define NODE_SMEM 104960

__device__ __forceinline__ void node_body(
    const float* __restrict__ A, float* __restrict__ out, int ostride,
    const uint* __restrict__ WhU, const uint* __restrict__ WlU,
    const float* __restrict__ bias, int relu)
{
    extern __shared__ char sm[];
    const int tid = threadIdx.x;
    const int wid = tid >> 5, lane = tid & 31;
    const uint32_t base = sm_addr(sm);

    for (int i = tid; i < 128 * 64; i += 256) {
        const int k = i >> 6, n2 = i & 63;
        ((uint*)(sm + NS_WH))[k * 68 + n2] = WhU[i];
        ((uint*)(sm + NS_WL))[k * 68 + n2] = WlU[i];
    }
    if (tid < 128) ((float*)(sm + NS_B))[tid] = bias[tid];
    __syncthreads();

    const float* sb = (const float*)(sm + NS_B);
    const int m0 = (wid & 1) * 32, n0 = (wid >> 1) * 32;
    const uint32_t aOff = (uint32_t)(m0 + (lane & 15)) * N_AW + (lane >> 4) * 16;
    const uint32_t bOff = (uint32_t)(lane & 15) * 272 + n0 * 2 + (lane >> 4) * 16;
    const uint32_t aH = base + NS_AH, aL = base + NS_AL;
    const uint32_t wH = base + NS_WH, wL = base + NS_WL;

    const int ntiles = (N_NODES + 63) / 64;  // 782
    for (int t = blockIdx.x; t < ntiles; t += gridDim.x) {
        const int r0g = t * 64;
        {   // load + split A rows
            const int trow = tid >> 2, qq = tid & 3;
            const int rg = r0g + trow;
            const uint b0 = (uint)trow * N_AW + qq * 64;
            if (rg < N_NODES) {
                const float4* hp = (const float4*)(A + (size_t)rg * 128) + qq * 8;
                #pragma unroll
                for (int i = 0; i < 8; i++) {
                    uint2 H, L; split_f4(hp[i], H, L);
                    *(uint2*)(sm + NS_AH + b0 + i * 8) = H;
                    *(uint2*)(sm + NS_AL + b0 + i * 8) = L;
                }
            } else {
                const uint2 z = make_uint2(0u, 0u);
                #pragma unroll
                for (int i = 0; i < 8; i++) {
                    *(uint2*)(sm + NS_AH + b0 + i * 8) = z;
                    *(uint2*)(sm + NS_AL + b0 + i * 8) = z;
                }
            }
        }
        __syncthreads();

        float acc[8][4];
        #pragma unroll
        for (int i = 0; i < 8; i++) { acc[i][0]=0; acc[i][1]=0; acc[i][2]=0; acc[i][3]=0; }
        #pragma unroll 1
        for (int p = 0; p < 3; p++)
            wgemm<8, 4, N_AW>(&acc[0][0], (p == 2) ? aL : aH,
                              (p == 1) ? wL : wH, aOff, bOff);
        __syncthreads();

        #pragma unroll
        for (int mt = 0; mt < 2; mt++)
            #pragma unroll
            for (int nt = 0; nt < 4; nt++) {
                float* a4 = acc[mt * 4 + nt];
                const int col = n0 + nt * 8 + 2 * (lane & 3);
                const int r = m0 + mt * 16 + (lane >> 2);
                const int rg0 = r0g + r, rg1 = rg0 + 8;
                float v0 = a4[0] + sb[col], v1 = a4[1] + sb[col + 1];
                float v2 = a4[2] + sb[col], v3 = a4[3] + sb[col + 1];
                if (relu) {
                    v0 = fmaxf(v0, 0.f); v1 = fmaxf(v1, 0.f);
                    v2 = fmaxf(v2, 0.f); v3 = fmaxf(v3, 0.f);
                }
                if (rg0 < N_NODES)
                    *(float2*)(out + (size_t)rg0 * ostride + col) = make_float2(v0, v1);
                if (rg1 < N_NODES)
                    *(float2*)(out + (size_t)rg1 * ostride + col) = make_float2(v2, v3);
            }
    }
}

__global__ __launch_bounds__(256, 2) void lin_mma_kernel(
    const float* __restrict__ x, const float* __restrict__ b)
{
    node_body(x, g_h, 128, (const uint*)(g_wh + OFF_LIN),
              (const uint*)(g_wl + OFF_LIN), b, 1);
}

__global__ __launch_bounds__(256, 2) void gru_mma_kernel(
    int l, const float* __restrict__ bih, const float* __restrict__ bhh)
{
    const int which = blockIdx.y / 3, gate = blockIdx.y % 3;
    const float* A = which ? g_h : g_agg;
    float* out = (which ? g_gh : g_gi) + gate * 128;
    const size_t wOff = (size_t)(which ? OFF_WHH : OFF_WIH) + (size_t)(l * 3 + gate) * 16384;
    const float* bias = (which ? bhh : bih) + gate * 128;
    node_body(A, out, 384, (const uint*)(g_wh + wOff), (const uint*)(g_wl + wOff), bias, 0);
}

// ============================================================================
// fused GRU gates + BatchNorm + residual
// ============================================================================
__global__ void gru_gate_kernel(
    const float* __restrict__ gamma, const float* __restrict__ beta,
    const float* __restrict__ mean, const float* __restrict__ var)
{
    const int idx = blockIdx.x * blockDim.x + threadIdx.x;
    if (idx >= N_NODES * HIDDEN) return;
    const int c = idx & 127;
    const size_t n = (size_t)(idx >> 7);
    const float* gi = g_gi + n * 384;
    const float* gh = g_gh + n * 384;
    const float hv = g_h[idx];
    const float r = 1.f / (1.f + expf(-(gi[c] + gh[c])));
    const float z = 1.f / (1.f + expf(-(gi[128 + c] + gh[128 + c])));
    const float nn = tanhf(gi[256 + c] + r * gh[256 + c]);
    const float hnew = (1.f - z) * nn + z * hv;
    const float bn = (hnew - mean[c]) * rsqrtf(var[c] + 1e-5f) * gamma[c] + beta[c];
    g_h[idx] = hv + bn;
}

// ---------------- aux kernels ----------------
__global__ void zero_agg_kernel() {
    const int idx = blockIdx.x * blockDim.x + threadIdx.x;
    if (idx < N_NODES * HIDDEN / 4)
        ((float4*)g_agg)[idx] = make_float4(0.f, 0.f, 0.f, 0.f);
}

__global__ void init_readout_kernel() {
    const int idx = blockIdx.x * blockDim.x + threadIdx.x;
    if (idx < N_GRAPHS * HIDDEN) { g_zsum[idx] = 0.f; g_zmax[idx] = 0x00800000u; }
    if (idx < N_GRAPHS) g_cnt[idx] = 0.f;
}

__global__ void seg_reduce_kernel(const int* __restrict__ batch) {
    const int gid = blockIdx.x * blockDim.x + threadIdx.x;
    if (gid >= N_NODES * 32) return;
    const int n = gid >> 5, q = gid & 31;
    const int g = batch[n];
    const float4 hv = *(const float4*)(g_h + (size_t)n * 128 + q * 4);
    red_add_v4(g_zsum + g * 128 + q * 4, hv.x, hv.y, hv.z, hv.w);
    unsigned* zm = g_zmax + g * 128 + q * 4;
    atomicMax(zm + 0, fenc(hv.x)); atomicMax(zm + 1, fenc(hv.y));
    atomicMax(zm + 2, fenc(hv.z)); atomicMax(zm + 3, fenc(hv.w));
    if (q == 0) atomicAdd(g_cnt + g, 1.f);
}

__global__ void readout_kernel(const float* __restrict__ ro_w,
                               const float* __restrict__ ro_b,
                               float* __restrict__ out)
{
    __shared__ float sbuf[256];
    const int g = blockIdx.x, j = threadIdx.x;
    const float c = g_cnt[g];
    const float inv = 1.f / fmaxf(c, 1.f);
    sbuf[j]       = g_zsum[g * 128 + j] * inv;
    sbuf[128 + j] = (c > 0.f) ? fdec(g_zmax[g * 128 + j]) : 0.f;
    __syncthreads();
    float acc = ro_b[j];
    #pragma unroll 8
    for (int k = 0; k < 256; k++) acc = fmaf(sbuf[k], ro_w[k * 128 + j], acc);
    out[g * 128 + j] = fmaxf(acc, 0.f);
}

// ============================================================================
extern "C" void kernel_launch(void* const* d_in, const int* in_sizes, int n_in,
                              void* d_out, int out_size)
{
    const int shift = (in_sizes[4] == 1) ? 1 : 0;
    const float* x         = (const float*)d_in[0];
    const int*   edge_idx  = (const int*)  d_in[1];
    const float* edge_attr = (const float*)d_in[2];
    const int*   batch     = (const int*)  d_in[3];
    const float* lin_in_w  = (const float*)d_in[4 + shift];
    const float* lin_in_b  = (const float*)d_in[5 + shift];
    const float* msg_w1    = (const float*)d_in[6 + shift];
    const float* msg_b1    = (const float*)d_in[7 + shift];
    const float* msg_w2    = (const float*)d_in[8 + shift];
    const float* msg_b2    = (const float*)d_in[9 + shift];
    const float* bn_gamma  = (const float*)d_in[10 + shift];
    const float* bn_beta   = (const float*)d_in[11 + shift];
    const float* bn_mean   = (const float*)d_in[12 + shift];
    const float* bn_var    = (const float*)d_in[13 + shift];
    const float* gru_wih   = (const float*)d_in[14 + shift];
    const float* gru_whh   = (const float*)d_in[15 + shift];
    const float* gru_bih   = (const float*)d_in[16 + shift];
    const float* gru_bhh   = (const float*)d_in[17 + shift];
    const float* ro_w      = (const float*)d_in[18 + shift];
    const float* ro_b      = (const float*)d_in[19 + shift];
    float* out = (float*)d_out;

    static bool inited = false;
    if (!inited) {
        cudaFuncSetAttribute(edge_mma_kernel, cudaFuncAttributeMaxDynamicSharedMemorySize, EDGE_SMEM);
        cudaFuncSetAttribute(lin_mma_kernel,  cudaFuncAttributeMaxDynamicSharedMemorySize, NODE_SMEM);
        cudaFuncSetAttribute(gru_mma_kernel,  cudaFuncAttributeMaxDynamicSharedMemorySize, NODE_SMEM);
        inited = true;
    }

    const int* src = edge_idx;
    const int* dst = edge_idx + N_EDGES;

    conv_w_kernel<<<dim3(576, 5), 256>>>(lin_in_w, msg_w1, msg_w2, gru_wih, gru_whh);
    lin_mma_kernel<<<296, 256, NODE_SMEM>>>(x, lin_in_b);

    for (int l = 0; l < N_LAYERS; l++) {
        zero_agg_kernel<<<(N_NODES * HIDDEN / 4 + 255) / 256, 256>>>();
        edge_mma_kernel<<<148, 256, EDGE_SMEM>>>(
            src, dst, edge_attr, l, msg_b1 + l * 128, msg_b2 + l * 128);
        gru_mma_kernel<<<dim3(296, 6), 256, NODE_SMEM>>>(
            l, gru_bih + (size_t)l * 384, gru_bhh + (size_t)l * 384);
        gru_gate_kernel<<<(N_NODES * HIDDEN + 255) / 256, 256>>>(
            bn_gamma + l * 128, bn_beta + l * 128, bn_mean + l * 128, bn_var + l * 128);
    }

    init_readout_kernel<<<(N_GRAPHS * HIDDEN + 255) / 256, 256>>>();
    seg_reduce_kernel<<<(N_NODES * 32 + 255) / 256, 256>>>(batch);
    readout_kernel<<<N_GRAPHS, 128>>>(ro_w, ro_b, out);
}

// round 14
// speedup vs baseline: 1.0689x; 1.0300x over previous
#include <cuda_runtime.h>
#include <cuda_bf16.h>
#include <cstdint>
#include <math.h>

#define N_NODES 50000
#define N_EDGES 800000
#define IN_DIM 128
#define EDGE_DIM 16
#define HIDDEN 128
#define N_LAYERS 3
#define N_GRAPHS 256

typedef unsigned int uint;

// ---------------- scratch (device globals: allocation-free) ----------------
__device__ float g_h[(size_t)N_NODES * HIDDEN];
__device__ float g_agg[(size_t)N_NODES * HIDDEN];
__device__ float g_gi[(size_t)N_NODES * 3 * HIDDEN];
__device__ float g_gh[(size_t)N_NODES * 3 * HIDDEN];
__device__ float g_zsum[N_GRAPHS * HIDDEN];
__device__ unsigned g_zmax[N_GRAPHS * HIDDEN];
__device__ float g_cnt[N_GRAPHS];

// bf16 split weight staging: [K][128] row-major per matrix
#define OFF_LIN 0
#define OFF_M1  16384
#define OFF_M2  71680
#define OFF_WIH 120832
#define OFF_WHH 268288
#define W_TOTAL 415744
__device__ __nv_bfloat16 g_wh[W_TOTAL];
__device__ __nv_bfloat16 g_wl[W_TOTAL];

// ---------------- misc helpers ----------------
__device__ __forceinline__ unsigned fenc(float f) {
    unsigned u = __float_as_uint(f);
    return (u & 0x80000000u) ? ~u : (u | 0x80000000u);
}
__device__ __forceinline__ float fdec(unsigned u) {
    return __uint_as_float((u & 0x80000000u) ? (u ^ 0x80000000u) : ~u);
}
__device__ __forceinline__ void red_add_v4(float* p, float a, float b, float c, float d) {
    asm volatile("red.global.add.v4.f32 [%0],{%1,%2,%3,%4};"
                 :: "l"(p), "f"(a), "f"(b), "f"(c), "f"(d) : "memory");
}

// split two fp32 into packed bf16 hi-word and lo-word (residual)
__device__ __forceinline__ void split2p(float a, float b, uint& h, uint& l) {
    __nv_bfloat162 t = __floats2bfloat162_rn(a, b);
    h = *reinterpret_cast<uint*>(&t);
    float ah = __uint_as_float(h << 16);
    float bh = __uint_as_float(h & 0xffff0000u);
    __nv_bfloat162 t2 = __floats2bfloat162_rn(a - ah, b - bh);
    l = *reinterpret_cast<uint*>(&t2);
}
__device__ __forceinline__ void split_f4(float4 f, uint2& H, uint2& L) {
    split2p(f.x, f.y, H.x, L.x);
    split2p(f.z, f.w, H.y, L.y);
}

// ---------------- mma / ldmatrix primitives (sm_80-level PTX) ----------------
__device__ __forceinline__ uint32_t sm_addr(const void* p) {
    return (uint32_t)__cvta_generic_to_shared(p);
}
__device__ __forceinline__ void ldsm4(uint* r, uint32_t a) {
    asm volatile("ldmatrix.sync.aligned.m8n8.x4.shared.b16 {%0,%1,%2,%3},[%4];"
        : "=r"(r[0]), "=r"(r[1]), "=r"(r[2]), "=r"(r[3]) : "r"(a));
}
__device__ __forceinline__ void ldsm4t(uint* r, uint32_t a) {
    asm volatile("ldmatrix.sync.aligned.m8n8.x4.trans.shared.b16 {%0,%1,%2,%3},[%4];"
        : "=r"(r[0]), "=r"(r[1]), "=r"(r[2]), "=r"(r[3]) : "r"(a));
}
__device__ __forceinline__ void mmabf16(float* d, const uint* a, const uint* b) {
    asm volatile("mma.sync.aligned.m16n8k16.row.col.f32.bf16.bf16.f32 "
        "{%0,%1,%2,%3},{%4,%5,%6,%7},{%8,%9},{%0,%1,%2,%3};"
        : "+f"(d[0]), "+f"(d[1]), "+f"(d[2]), "+f"(d[3])
        : "r"(a[0]), "r"(a[1]), "r"(a[2]), "r"(a[3]), "r"(b[0]), "r"(b[1]));
}

// warp-level GEMM fragment: 2 m16-tiles x NT n8-tiles, NK16 k-steps.
template<int NK16, int NT, int ASTR>
__device__ __forceinline__ void wgemm(float* acc, uint32_t Ab, uint32_t Bb,
                                      uint32_t aOff, uint32_t bOff) {
    #pragma unroll
    for (int k = 0; k < NK16; k++) {
        uint a[2][4];
        ldsm4(a[0], Ab + aOff + k * 32);
        ldsm4(a[1], Ab + aOff + k * 32 + 16 * ASTR);
        uint bb[NT][2];
        #pragma unroll
        for (int p2 = 0; p2 < NT / 2; p2++) {
            uint r[4];
            ldsm4t(r, Bb + bOff + k * 16 * 272 + p2 * 32);
            bb[2*p2][0] = r[0]; bb[2*p2][1] = r[1];
            bb[2*p2+1][0] = r[2]; bb[2*p2+1][1] = r[3];
        }
        #pragma unroll
        for (int mt = 0; mt < 2; mt++)
            #pragma unroll
            for (int nt = 0; nt < NT; nt++)
                mmabf16(acc + (mt * NT + nt) * 4, a[mt], bb[nt]);
    }
}

// ============================================================================
// weight conversion: fp32 -> canonical [K][128] bf16 hi/lo staging
// ============================================================================
__global__ void conv_w_kernel(const float* __restrict__ lin_w,
                              const float* __restrict__ m1,
                              const float* __restrict__ m2,
                              const float* __restrict__ wih,
                              const float* __restrict__ whh)
{
    const int i = blockIdx.x * 256 + threadIdx.x;
    const int seg = blockIdx.y;
    int sz, off; float v;
    switch (seg) {
    case 0: sz = 16384;  off = OFF_LIN; if (i >= sz) return; v = lin_w[i]; break;
    case 1: sz = 55296;  off = OFF_M1;  if (i >= sz) return; v = m1[i]; break;
    case 2: sz = 49152;  off = OFF_M2;  if (i >= sz) return; v = m2[i]; break;
    default: {
        sz = 147456; off = (seg == 3) ? OFF_WIH : OFF_WHH;
        if (i >= sz) return;
        const float* W = (seg == 3) ? wih : whh;
        const int m = i >> 14, t = i & 16383, k = t >> 7, j = t & 127;
        v = W[(m / 3) * 49152 + ((m % 3) * 128 + j) * 128 + k];
        break;
    }}
    __nv_bfloat16 h = __float2bfloat16(v);
    float r = v - __bfloat162float(h);
    g_wh[off + i] = h;
    g_wl[off + i] = __float2bfloat16(r);
}

// ============================================================================
// edge message kernel (mma, software-pipelined): 64-edge tiles, 256 thr =
// 8 warps (warp: 32x32). Double-buffered A; prefetch next tile's gather
// during GEMMs. Scatter via red.global.add.v4.f32.
// ============================================================================
#define E_AW  304      // A stride bytes (152 bf16)
#define S_W1H 0
#define S_W1L 39168
#define S_W2H 78336
#define S_W2L 113152
#define S_A0H 147968
#define S_A0L 167424
#define S_A1H 186880
#define S_A1L 206336
#define S_B1  225792
#define S_B2  226304
#define S_DST 226816   // 2 x 64 ints
#define EDGE_SMEM 227328

__global__ __launch_bounds__(256, 1) void edge_mma_kernel(
    const int* __restrict__ src, const int* __restrict__ dst,
    const float* __restrict__ edge_attr, int l,
    const float* __restrict__ b1, const float* __restrict__ b2)
{
    extern __shared__ char sm[];
    const int tid = threadIdx.x;
    const int wid = tid >> 5, lane = tid & 31;
    const uint32_t base = sm_addr(sm);

    // ---- copy split weights to smem (padded stride 136 elems) ----
    {
        const uint* w1h = (const uint*)(g_wh + OFF_M1 + (size_t)l * 18432);
        const uint* w1l = (const uint*)(g_wl + OFF_M1 + (size_t)l * 18432);
        for (int i = tid; i < 144 * 64; i += 256) {
            const int k = i >> 6, n2 = i & 63;
            ((uint*)(sm + S_W1H))[k * 68 + n2] = w1h[i];
            ((uint*)(sm + S_W1L))[k * 68 + n2] = w1l[i];
        }
        const uint* w2h = (const uint*)(g_wh + OFF_M2 + (size_t)l * 16384);
        const uint* w2l = (const uint*)(g_wl + OFF_M2 + (size_t)l * 16384);
        for (int i = tid; i < 128 * 64; i += 256) {
            const int k = i >> 6, n2 = i & 63;
            ((uint*)(sm + S_W2H))[k * 68 + n2] = w2h[i];
            ((uint*)(sm + S_W2L))[k * 68 + n2] = w2l[i];
        }
        if (tid < 128) {
            ((float*)(sm + S_B1))[tid] = b1[tid];
            ((float*)(sm + S_B2))[tid] = b2[tid];
        }
    }

    const float* sb1 = (const float*)(sm + S_B1);
    const float* sb2 = (const float*)(sm + S_B2);
    const int m0 = (wid & 1) * 32, n0 = (wid >> 1) * 32;
    const uint32_t aOff = (uint32_t)(m0 + (lane & 15)) * E_AW + (lane >> 4) * 16;
    const uint32_t bOff = (uint32_t)(lane & 15) * 272 + n0 * 2 + (lane >> 4) * 16;
    const uint32_t w1H = base + S_W1H, w1L = base + S_W1L;
    const uint32_t w2H = base + S_W2H, w2L = base + S_W2L;
    const int q = lane & 3, qodd = q & 1;
    const int grow = tid >> 2, gq = tid & 3;          // gather: 4 thr/row
    const uint gb0 = (uint)grow * E_AW + gq * 64;     // byte base in A buf

    const int ntiles = N_EDGES / 64;   // 12500
    const int step = gridDim.x;

    // ---- prologue: full gather of first tile into buf 0 ----
    int t = blockIdx.x;
    {
        const int e = t * 64 + grow;
        const int s = src[e];
        const float4* hp = (const float4*)(g_h + (size_t)s * 128) + gq * 8;
        #pragma unroll
        for (int i = 0; i < 8; i++) {
            uint2 H, L; split_f4(hp[i], H, L);
            *(uint2*)(sm + S_A0H + gb0 + i * 8) = H;
            *(uint2*)(sm + S_A0L + gb0 + i * 8) = L;
        }
        if (gq == 0) {
            const float4* ep = (const float4*)(edge_attr + (size_t)e * 16);
            #pragma unroll
            for (int i = 0; i < 4; i++) {
                uint2 H, L; split_f4(ep[i], H, L);
                *(uint2*)(sm + S_A0H + (uint)grow * E_AW + 256 + i * 8) = H;
                *(uint2*)(sm + S_A0L + (uint)grow * E_AW + 256 + i * 8) = L;
            }
        }
        if (tid < 64) ((int*)(sm + S_DST))[tid] = dst[t * 64 + tid];
    }
    __syncthreads();

    int cur = 0;
    for (; t < ntiles; t += step) {
        const int tn = t + step;
        const bool pfv = (tn < ntiles);
        const uint32_t aH = base + (cur ? S_A1H : S_A0H);
        const uint32_t aL = base + (cur ? S_A1L : S_A0L);
        const uint32_t nH = base + (cur ? S_A0H : S_A1H);
        const uint32_t nL = base + (cur ? S_A0L : S_A1L);
        const int* sDstC = (const int*)(sm + S_DST) + cur * 64;
        int* sDstN = (int*)(sm + S_DST) + (cur ^ 1) * 64;

        // ---- prefetch issue #1: first half of h rows + ea + dst ----
        const float4* hpn = 0;
        float4 pf[4], pe[4];
        int pd = 0;
        if (pfv) {
            const int e = tn * 64 + grow;
            const int s = src[e];
            hpn = (const float4*)(g_h + (size_t)s * 128) + gq * 8;
            #pragma unroll
            for (int i = 0; i < 4; i++) pf[i] = hpn[i];
            if (gq == 0) {
                const float4* ep = (const float4*)(edge_attr + (size_t)e * 16);
                #pragma unroll
                for (int i = 0; i < 4; i++) pe[i] = ep[i];
            }
            if (tid < 64) pd = dst[tn * 64 + tid];
        }

        // ---- GEMM1 (K=144, 3-pass split) ----
        float acc[8][4];
        #pragma unroll
        for (int i = 0; i < 8; i++) { acc[i][0]=0; acc[i][1]=0; acc[i][2]=0; acc[i][3]=0; }
        #pragma unroll 1
        for (int p = 0; p < 3; p++)
            wgemm<9, 4, E_AW>(&acc[0][0], (p == 2) ? aL : aH,
                              (p == 1) ? w1L : w1H, aOff, bOff);
        __syncthreads();   // all warps done reading A before Hid overwrite

        // ---- epilogue1: relu(+b1) -> re-split into cur buf ----
        #pragma unroll
        for (int mt = 0; mt < 2; mt++)
            #pragma unroll
            for (int nt = 0; nt < 4; nt++) {
                float* a4 = acc[mt * 4 + nt];
                const int col = n0 + nt * 8 + 2 * q;
                const int r0 = m0 + mt * 16 + (lane >> 2);
                float v0 = fmaxf(a4[0] + sb1[col], 0.f), v1 = fmaxf(a4[1] + sb1[col+1], 0.f);
                float v2 = fmaxf(a4[2] + sb1[col], 0.f), v3 = fmaxf(a4[3] + sb1[col+1], 0.f);
                uint h, lo;
                split2p(v0, v1, h, lo);
                *(uint*)(aH - base + sm + (uint)r0 * E_AW + col * 2) = h;
                *(uint*)(aL - base + sm + (uint)r0 * E_AW + col * 2) = lo;
                split2p(v2, v3, h, lo);
                *(uint*)(aH - base + sm + (uint)(r0 + 8) * E_AW + col * 2) = h;
                *(uint*)(aL - base + sm + (uint)(r0 + 8) * E_AW + col * 2) = lo;
            }

        // ---- drain prefetch #1 into next buf; issue prefetch #2 ----
        if (pfv) {
            #pragma unroll
            for (int i = 0; i < 4; i++) {
                uint2 H, L; split_f4(pf[i], H, L);
                *(uint2*)(nH - base + sm + gb0 + i * 8) = H;
                *(uint2*)(nL - base + sm + gb0 + i * 8) = L;
            }
            if (gq == 0) {
                #pragma unroll
                for (int i = 0; i < 4; i++) {
                    uint2 H, L; split_f4(pe[i], H, L);
                    *(uint2*)(nH - base + sm + (uint)grow * E_AW + 256 + i * 8) = H;
                    *(uint2*)(nL - base + sm + (uint)grow * E_AW + 256 + i * 8) = L;
                }
            }
            if (tid < 64) sDstN[tid] = pd;
            #pragma unroll
            for (int i = 0; i < 4; i++) pf[i] = hpn[4 + i];
        }
        __syncthreads();   // Hid visible to all warps

        // ---- GEMM2 (K=128, 3-pass split) ----
        #pragma unroll
        for (int i = 0; i < 8; i++) { acc[i][0]=0; acc[i][1]=0; acc[i][2]=0; acc[i][3]=0; }
        #pragma unroll 1
        for (int p = 0; p < 3; p++)
            wgemm<8, 4, E_AW>(&acc[0][0], (p == 2) ? aL : aH,
                              (p == 1) ? w2L : w2H, aOff, bOff);

        // ---- epilogue2: +b2, lane-pair shuffle -> one v4 reduction each ----
        #pragma unroll
        for (int mt = 0; mt < 2; mt++)
            #pragma unroll
            for (int nt = 0; nt < 4; nt++) {
                float* a4 = acc[mt * 4 + nt];
                const int col  = n0 + nt * 8 + 2 * q;
                const int colb = n0 + nt * 8 + 2 * (q & ~1);
                const int r0 = m0 + mt * 16 + (lane >> 2);
                const float v0 = a4[0] + sb2[col], v1 = a4[1] + sb2[col + 1];
                const float v2 = a4[2] + sb2[col], v3 = a4[3] + sb2[col + 1];
                const float s0 = qodd ? v0 : v2;
                const float s1 = qodd ? v1 : v3;
                const float x0 = __shfl_xor_sync(0xffffffffu, s0, 1);
                const float x1 = __shfl_xor_sync(0xffffffffu, s1, 1);
                const int drow = qodd ? sDstC[r0 + 8] : sDstC[r0];
                float* p = g_agg + (size_t)drow * 128 + colb;
                if (qodd) red_add_v4(p, x0, x1, v2, v3);
                else      red_add_v4(p, v0, v1, x0, x1);
            }

        // ---- drain prefetch #2 into next buf ----
        if (pfv) {
            #pragma unroll
            for (int i = 0; i < 4; i++) {
                uint2 H, L; split_f4(pf[i], H, L);
                *(uint2*)(nH - base + sm + gb0 + 32 + i * 8) = H;
                *(uint2*)(nL - base + sm + gb0 + 32 + i * 8) = L;
            }
        }
        __syncthreads();   // next buf complete before next iteration's GEMM1
        cur ^= 1;
    }
}

// ============================================================================
// node GEMM body (mma): out[n,128] = act(A[n,128] @ W + b); 64-row tiles,
// 256 thr = 8 warps (warp 32x32), 2 CTAs/SM.
// ============================================================================
#define N_AW 272                 // A stride bytes (136 bf16)
#define NS_WH 0
#define NS_WL 34816
#define NS_AH 69632
#define NS_AL 87040
#define NS_B  104448
#define NODE_SMEM 104960

__device__ __forceinline__ void node_body(
    const float* __restrict__ A, float* __restrict__ out, int ostride,
    const uint* __restrict__ WhU, const uint* __restrict__ WlU,
    const float* __restrict__ bias, int relu)
{
    extern __shared__ char sm[];
    const int tid = threadIdx.x;
    const int wid = tid >> 5, lane = tid & 31;
    const uint32_t base = sm_addr(sm);

    for (int i = tid; i < 128 * 64; i += 256) {
        const int k = i >> 6, n2 = i & 63;
        ((uint*)(sm + NS_WH))[k * 68 + n2] = WhU[i];
        ((uint*)(sm + NS_WL))[k * 68 + n2] = WlU[i];
    }
    if (tid < 128) ((float*)(sm + NS_B))[tid] = bias[tid];
    __syncthreads();

    const float* sb = (const float*)(sm + NS_B);
    const int m0 = (wid & 1) * 32, n0 = (wid >> 1) * 32;
    const uint32_t aOff = (uint32_t)(m0 + (lane & 15)) * N_AW + (lane >> 4) * 16;
    const uint32_t bOff = (uint32_t)(lane & 15) * 272 + n0 * 2 + (lane >> 4) * 16;
    const uint32_t aH = base + NS_AH, aL = base + NS_AL;
    const uint32_t wH = base + NS_WH, wL = base + NS_WL;

    const int ntiles = (N_NODES + 63) / 64;  // 782
    for (int t = blockIdx.x; t < ntiles; t += gridDim.x) {
        const int r0g = t * 64;
        {   // load + split A rows
            const int trow = tid >> 2, qq = tid & 3;
            const int rg = r0g + trow;
            const uint b0 = (uint)trow * N_AW + qq * 64;
            if (rg < N_NODES) {
                const float4* hp = (const float4*)(A + (size_t)rg * 128) + qq * 8;
                #pragma unroll
                for (int i = 0; i < 8; i++) {
                    uint2 H, L; split_f4(hp[i], H, L);
                    *(uint2*)(sm + NS_AH + b0 + i * 8) = H;
                    *(uint2*)(sm + NS_AL + b0 + i * 8) = L;
                }
            } else {
                const uint2 z = make_uint2(0u, 0u);
                #pragma unroll
                for (int i = 0; i < 8; i++) {
                    *(uint2*)(sm + NS_AH + b0 + i * 8) = z;
                    *(uint2*)(sm + NS_AL + b0 + i * 8) = z;
                }
            }
        }
        __syncthreads();

        float acc[8][4];
        #pragma unroll
        for (int i = 0; i < 8; i++) { acc[i][0]=0; acc[i][1]=0; acc[i][2]=0; acc[i][3]=0; }
        #pragma unroll 1
        for (int p = 0; p < 3; p++)
            wgemm<8, 4, N_AW>(&acc[0][0], (p == 2) ? aL : aH,
                              (p == 1) ? wL : wH, aOff, bOff);
        __syncthreads();

        #pragma unroll
        for (int mt = 0; mt < 2; mt++)
            #pragma unroll
            for (int nt = 0; nt < 4; nt++) {
                float* a4 = acc[mt * 4 + nt];
                const int col = n0 + nt * 8 + 2 * (lane & 3);
                const int r = m0 + mt * 16 + (lane >> 2);
                const int rg0 = r0g + r, rg1 = rg0 + 8;
                float v0 = a4[0] + sb[col], v1 = a4[1] + sb[col + 1];
                float v2 = a4[2] + sb[col], v3 = a4[3] + sb[col + 1];
                if (relu) {
                    v0 = fmaxf(v0, 0.f); v1 = fmaxf(v1, 0.f);
                    v2 = fmaxf(v2, 0.f); v3 = fmaxf(v3, 0.f);
                }
                if (rg0 < N_NODES)
                    *(float2*)(out + (size_t)rg0 * ostride + col) = make_float2(v0, v1);
                if (rg1 < N_NODES)
                    *(float2*)(out + (size_t)rg1 * ostride + col) = make_float2(v2, v3);
            }
    }
}

__global__ __launch_bounds__(256, 2) void lin_mma_kernel(
    const float* __restrict__ x, const float* __restrict__ b)
{
    node_body(x, g_h, 128, (const uint*)(g_wh + OFF_LIN),
              (const uint*)(g_wl + OFF_LIN), b, 1);
}

__global__ __launch_bounds__(256, 2) void gru_mma_kernel(
    int l, const float* __restrict__ bih, const float* __restrict__ bhh)
{
    const int which = blockIdx.y / 3, gate = blockIdx.y % 3;
    const float* A = which ? g_h : g_agg;
    float* out = (which ? g_gh : g_gi) + gate * 128;
    const size_t wOff = (size_t)(which ? OFF_WHH : OFF_WIH) + (size_t)(l * 3 + gate) * 16384;
    const float* bias = (which ? bhh : bih) + gate * 128;
    node_body(A, out, 384, (const uint*)(g_wh + wOff), (const uint*)(g_wl + wOff), bias, 0);
}

// ============================================================================
// fused GRU gates + BatchNorm + residual
// ============================================================================
__global__ void gru_gate_kernel(
    const float* __restrict__ gamma, const float* __restrict__ beta,
    const float* __restrict__ mean, const float* __restrict__ var)
{
    const int idx = blockIdx.x * blockDim.x + threadIdx.x;
    if (idx >= N_NODES * HIDDEN) return;
    const int c = idx & 127;
    const size_t n = (size_t)(idx >> 7);
    const float* gi = g_gi + n * 384;
    const float* gh = g_gh + n * 384;
    const float hv = g_h[idx];
    const float r = 1.f / (1.f + expf(-(gi[c] + gh[c])));
    const float z = 1.f / (1.f + expf(-(gi[128 + c] + gh[128 + c])));
    const float nn = tanhf(gi[256 + c] + r * gh[256 + c]);
    const float hnew = (1.f - z) * nn + z * hv;
    const float bn = (hnew - mean[c]) * rsqrtf(var[c] + 1e-5f) * gamma[c] + beta[c];
    g_h[idx] = hv + bn;
}

// ---------------- aux kernels ----------------
__global__ void zero_agg_kernel() {
    const int idx = blockIdx.x * blockDim.x + threadIdx.x;
    if (idx < N_NODES * HIDDEN / 4)
        ((float4*)g_agg)[idx] = make_float4(0.f, 0.f, 0.f, 0.f);
}

__global__ void init_readout_kernel() {
    const int idx = blockIdx.x * blockDim.x + threadIdx.x;
    if (idx < N_GRAPHS * HIDDEN) { g_zsum[idx] = 0.f; g_zmax[idx] = 0x00800000u; }
    if (idx < N_GRAPHS) g_cnt[idx] = 0.f;
}

__global__ void seg_reduce_kernel(const int* __restrict__ batch) {
    const int gid = blockIdx.x * blockDim.x + threadIdx.x;
    if (gid >= N_NODES * 32) return;
    const int n = gid >> 5, q = gid & 31;
    const int g = batch[n];
    const float4 hv = *(const float4*)(g_h + (size_t)n * 128 + q * 4);
    red_add_v4(g_zsum + g * 128 + q * 4, hv.x, hv.y, hv.z, hv.w);
    unsigned* zm = g_zmax + g * 128 + q * 4;
    atomicMax(zm + 0, fenc(hv.x)); atomicMax(zm + 1, fenc(hv.y));
    atomicMax(zm + 2, fenc(hv.z)); atomicMax(zm + 3, fenc(hv.w));
    if (q == 0) atomicAdd(g_cnt + g, 1.f);
}

__global__ void readout_kernel(const float* __restrict__ ro_w,
                               const float* __restrict__ ro_b,
                               float* __restrict__ out)
{
    __shared__ float sbuf[256];
    const int g = blockIdx.x, j = threadIdx.x;
    const float c = g_cnt[g];
    const float inv = 1.f / fmaxf(c, 1.f);
    sbuf[j]       = g_zsum[g * 128 + j] * inv;
    sbuf[128 + j] = (c > 0.f) ? fdec(g_zmax[g * 128 + j]) : 0.f;
    __syncthreads();
    float acc = ro_b[j];
    #pragma unroll 8
    for (int k = 0; k < 256; k++) acc = fmaf(sbuf[k], ro_w[k * 128 + j], acc);
    out[g * 128 + j] = fmaxf(acc, 0.f);
}

// ============================================================================
extern "C" void kernel_launch(void* const* d_in, const int* in_sizes, int n_in,
                              void* d_out, int out_size)
{
    const int shift = (in_sizes[4] == 1) ? 1 : 0;
    const float* x         = (const float*)d_in[0];
    const int*   edge_idx  = (const int*)  d_in[1];
    const float* edge_attr = (const float*)d_in[2];
    const int*   batch     = (const int*)  d_in[3];
    const float* lin_in_w  = (const float*)d_in[4 + shift];
    const float* lin_in_b  = (const float*)d_in[5 + shift];
    const float* msg_w1    = (const float*)d_in[6 + shift];
    const float* msg_b1    = (const float*)d_in[7 + shift];
    const float* msg_w2    = (const float*)d_in[8 + shift];
    const float* msg_b2    = (const float*)d_in[9 + shift];
    const float* bn_gamma  = (const float*)d_in[10 + shift];
    const float* bn_beta   = (const float*)d_in[11 + shift];
    const float* bn_mean   = (const float*)d_in[12 + shift];
    const float* bn_var    = (const float*)d_in[13 + shift];
    const float* gru_wih   = (const float*)d_in[14 + shift];
    const float* gru_whh   = (const float*)d_in[15 + shift];
    const float* gru_bih   = (const float*)d_in[16 + shift];
    const float* gru_bhh   = (const float*)d_in[17 + shift];
    const float* ro_w      = (const float*)d_in[18 + shift];
    const float* ro_b      = (const float*)d_in[19 + shift];
    float* out = (float*)d_out;

    static bool inited = false;
    if (!inited) {
        cudaFuncSetAttribute(edge_mma_kernel, cudaFuncAttributeMaxDynamicSharedMemorySize, EDGE_SMEM);
        cudaFuncSetAttribute(lin_mma_kernel,  cudaFuncAttributeMaxDynamicSharedMemorySize, NODE_SMEM);
        cudaFuncSetAttribute(gru_mma_kernel,  cudaFuncAttributeMaxDynamicSharedMemorySize, NODE_SMEM);
        inited = true;
    }

    const int* src = edge_idx;
    const int* dst = edge_idx + N_EDGES;

    conv_w_kernel<<<dim3(576, 5), 256>>>(lin_in_w, msg_w1, msg_w2, gru_wih, gru_whh);
    lin_mma_kernel<<<296, 256, NODE_SMEM>>>(x, lin_in_b);

    for (int l = 0; l < N_LAYERS; l++) {
        zero_agg_kernel<<<(N_NODES * HIDDEN / 4 + 255) / 256, 256>>>();
        edge_mma_kernel<<<148, 256, EDGE_SMEM>>>(
            src, dst, edge_attr, l, msg_b1 + l * 128, msg_b2 + l * 128);
        gru_mma_kernel<<<dim3(296, 6), 256, NODE_SMEM>>>(
            l, gru_bih + (size_t)l * 384, gru_bhh + (size_t)l * 384);
        gru_gate_kernel<<<(N_NODES * HIDDEN + 255) / 256, 256>>>(
            bn_gamma + l * 128, bn_beta + l * 128, bn_mean + l * 128, bn_var + l * 128);
    }

    init_readout_kernel<<<(N_GRAPHS * HIDDEN + 255) / 256, 256>>>();
    seg_reduce_kernel<<<(N_NODES * 32 + 255) / 256, 256>>>(batch);
    readout_kernel<<<N_GRAPHS, 128>>>(ro_w, ro_b, out);
}

// round 15
// speedup vs baseline: 1.3829x; 1.2937x over previous
#include <cuda_runtime.h>
#include <cuda_fp16.h>
#include <cstdint>
#include <math.h>

#define N_NODES 50000
#define N_EDGES 800000
#define IN_DIM 128
#define EDGE_DIM 16
#define HIDDEN 128
#define N_LAYERS 3
#define N_GRAPHS 256

typedef unsigned int uint;

// ---------------- scratch (device globals: allocation-free) ----------------
__device__ float g_h[(size_t)N_NODES * HIDDEN];
__device__ float g_agg[(size_t)N_NODES * HIDDEN];
__device__ float g_gi[(size_t)N_NODES * 3 * HIDDEN];
__device__ float g_gh[(size_t)N_NODES * 3 * HIDDEN];
__device__ float g_zsum[N_GRAPHS * HIDDEN];
__device__ unsigned g_zmax[N_GRAPHS * HIDDEN];
__device__ float g_cnt[N_GRAPHS];

// fp16 split weight staging: [K][128] row-major per matrix (hi + residual lo)
#define OFF_LIN 0
#define OFF_M1  16384
#define OFF_M2  71680
#define OFF_WIH 120832
#define OFF_WHH 268288
#define W_TOTAL 415744
__device__ __half g_wh[W_TOTAL];
__device__ __half g_wl[W_TOTAL];

// ---------------- misc helpers ----------------
__device__ __forceinline__ unsigned fenc(float f) {
    unsigned u = __float_as_uint(f);
    return (u & 0x80000000u) ? ~u : (u | 0x80000000u);
}
__device__ __forceinline__ float fdec(unsigned u) {
    return __uint_as_float((u & 0x80000000u) ? (u ^ 0x80000000u) : ~u);
}
__device__ __forceinline__ void red_add_v4(float* p, float a, float b, float c, float d) {
    asm volatile("red.global.add.v4.f32 [%0],{%1,%2,%3,%4};"
                 :: "l"(p), "f"(a), "f"(b), "f"(c), "f"(d) : "memory");
}
// pack two floats into one half2 word
__device__ __forceinline__ uint h2w(float a, float b) {
    __half2 t = __floats2half2_rn(a, b);
    return *reinterpret_cast<uint*>(&t);
}
__device__ __forceinline__ uint2 f4h(float4 f) {
    return make_uint2(h2w(f.x, f.y), h2w(f.z, f.w));
}

// ---------------- mma / ldmatrix primitives (sm_80-level PTX) ----------------
__device__ __forceinline__ uint32_t sm_addr(const void* p) {
    return (uint32_t)__cvta_generic_to_shared(p);
}
__device__ __forceinline__ void ldsm4(uint* r, uint32_t a) {
    asm volatile("ldmatrix.sync.aligned.m8n8.x4.shared.b16 {%0,%1,%2,%3},[%4];"
        : "=r"(r[0]), "=r"(r[1]), "=r"(r[2]), "=r"(r[3]) : "r"(a));
}
__device__ __forceinline__ void ldsm4t(uint* r, uint32_t a) {
    asm volatile("ldmatrix.sync.aligned.m8n8.x4.trans.shared.b16 {%0,%1,%2,%3},[%4];"
        : "=r"(r[0]), "=r"(r[1]), "=r"(r[2]), "=r"(r[3]) : "r"(a));
}
__device__ __forceinline__ void mmaf16(float* d, const uint* a, const uint* b) {
    asm volatile("mma.sync.aligned.m16n8k16.row.col.f32.f16.f16.f32 "
        "{%0,%1,%2,%3},{%4,%5,%6,%7},{%8,%9},{%0,%1,%2,%3};"
        : "+f"(d[0]), "+f"(d[1]), "+f"(d[2]), "+f"(d[3])
        : "r"(a[0]), "r"(a[1]), "r"(a[2]), "r"(a[3]), "r"(b[0]), "r"(b[1]));
}

// warp GEMM, 2-pass weight-split: acc += A*(Wh) + A*(Wl).
// A fragments loaded ONCE per k and reused across both passes.
template<int NK16, int NT, int ASTR>
__device__ __forceinline__ void wgemm2(float* acc, uint32_t Ab,
                                       uint32_t BbH, uint32_t BbL,
                                       uint32_t aOff, uint32_t bOff) {
    #pragma unroll
    for (int k = 0; k < NK16; k++) {
        uint a[2][4];
        ldsm4(a[0], Ab + aOff + k * 32);
        ldsm4(a[1], Ab + aOff + k * 32 + 16 * ASTR);
        uint bh[NT][2], bl[NT][2];
        #pragma unroll
        for (int p2 = 0; p2 < NT / 2; p2++) {
            uint r[4];
            ldsm4t(r, BbH + bOff + k * 16 * 272 + p2 * 32);
            bh[2*p2][0] = r[0]; bh[2*p2][1] = r[1];
            bh[2*p2+1][0] = r[2]; bh[2*p2+1][1] = r[3];
            ldsm4t(r, BbL + bOff + k * 16 * 272 + p2 * 32);
            bl[2*p2][0] = r[0]; bl[2*p2][1] = r[1];
            bl[2*p2+1][0] = r[2]; bl[2*p2+1][1] = r[3];
        }
        #pragma unroll
        for (int mt = 0; mt < 2; mt++)
            #pragma unroll
            for (int nt = 0; nt < NT; nt++) {
                mmaf16(acc + (mt * NT + nt) * 4, a[mt], bh[nt]);
                mmaf16(acc + (mt * NT + nt) * 4, a[mt], bl[nt]);
            }
    }
}

// ============================================================================
// weight conversion: fp32 -> canonical [K][128] fp16 hi/lo staging
// ============================================================================
__global__ void conv_w_kernel(const float* __restrict__ lin_w,
                              const float* __restrict__ m1,
                              const float* __restrict__ m2,
                              const float* __restrict__ wih,
                              const float* __restrict__ whh)
{
    const int i = blockIdx.x * 256 + threadIdx.x;
    const int seg = blockIdx.y;
    int sz, off; float v;
    switch (seg) {
    case 0: sz = 16384;  off = OFF_LIN; if (i >= sz) return; v = lin_w[i]; break;
    case 1: sz = 55296;  off = OFF_M1;  if (i >= sz) return; v = m1[i]; break;
    case 2: sz = 49152;  off = OFF_M2;  if (i >= sz) return; v = m2[i]; break;
    default: {
        sz = 147456; off = (seg == 3) ? OFF_WIH : OFF_WHH;
        if (i >= sz) return;
        const float* W = (seg == 3) ? wih : whh;
        const int m = i >> 14, t = i & 16383, k = t >> 7, j = t & 127;
        v = W[(m / 3) * 49152 + ((m % 3) * 128 + j) * 128 + k];
        break;
    }}
    __half h = __float2half_rn(v);
    g_wh[off + i] = h;
    g_wl[off + i] = __float2half_rn(v - __half2float(h));
}

// ============================================================================
// edge message kernel (mma, software-pipelined): 64-edge tiles, 256 thr =
// 8 warps (warp: 32x32). A single fp16 buffer, double-buffered; weights
// fp16 hi+lo 2-pass. Scatter via red.global.add.v4.f32.
// ============================================================================
#define E_AW  304      // A stride bytes (152 halves)
#define S_W1H 0
#define S_W1L 39168
#define S_W2H 78336
#define S_W2L 113152
#define S_A0  147968   // 64*304 = 19456
#define S_A1  167424
#define S_B1  186880
#define S_B2  187392
#define S_DST 187904   // 2 x 64 ints
#define EDGE_SMEM 188416

__global__ __launch_bounds__(256, 1) void edge_mma_kernel(
    const int* __restrict__ src, const int* __restrict__ dst,
    const float* __restrict__ edge_attr, int l,
    const float* __restrict__ b1, const float* __restrict__ b2)
{
    extern __shared__ char sm[];
    const int tid = threadIdx.x;
    const int wid = tid >> 5, lane = tid & 31;
    const uint32_t base = sm_addr(sm);

    // ---- copy split weights to smem (padded stride 136 halves) ----
    {
        const uint* w1h = (const uint*)(g_wh + OFF_M1 + (size_t)l * 18432);
        const uint* w1l = (const uint*)(g_wl + OFF_M1 + (size_t)l * 18432);
        for (int i = tid; i < 144 * 64; i += 256) {
            const int k = i >> 6, n2 = i & 63;
            ((uint*)(sm + S_W1H))[k * 68 + n2] = w1h[i];
            ((uint*)(sm + S_W1L))[k * 68 + n2] = w1l[i];
        }
        const uint* w2h = (const uint*)(g_wh + OFF_M2 + (size_t)l * 16384);
        const uint* w2l = (const uint*)(g_wl + OFF_M2 + (size_t)l * 16384);
        for (int i = tid; i < 128 * 64; i += 256) {
            const int k = i >> 6, n2 = i & 63;
            ((uint*)(sm + S_W2H))[k * 68 + n2] = w2h[i];
            ((uint*)(sm + S_W2L))[k * 68 + n2] = w2l[i];
        }
        if (tid < 128) {
            ((float*)(sm + S_B1))[tid] = b1[tid];
            ((float*)(sm + S_B2))[tid] = b2[tid];
        }
    }

    const float* sb1 = (const float*)(sm + S_B1);
    const float* sb2 = (const float*)(sm + S_B2);
    const int m0 = (wid & 1) * 32, n0 = (wid >> 1) * 32;
    const uint32_t aOff = (uint32_t)(m0 + (lane & 15)) * E_AW + (lane >> 4) * 16;
    const uint32_t bOff = (uint32_t)(lane & 15) * 272 + n0 * 2 + (lane >> 4) * 16;
    const uint32_t w1H = base + S_W1H, w1L = base + S_W1L;
    const uint32_t w2H = base + S_W2H, w2L = base + S_W2L;
    const int q = lane & 3, qodd = q & 1;
    const int grow = tid >> 2, gq = tid & 3;          // gather: 4 thr/row
    const uint gb0 = (uint)grow * E_AW + gq * 64;     // byte base in A buf

    const int ntiles = N_EDGES / 64;   // 12500
    const int step = gridDim.x;

    // ---- prologue: full gather of first tile into buf 0 ----
    int t = blockIdx.x;
    {
        const int e = t * 64 + grow;
        const int s = src[e];
        const float4* hp = (const float4*)(g_h + (size_t)s * 128) + gq * 8;
        #pragma unroll
        for (int i = 0; i < 8; i++)
            *(uint2*)(sm + S_A0 + gb0 + i * 8) = f4h(hp[i]);
        if (gq == 0) {
            const float4* ep = (const float4*)(edge_attr + (size_t)e * 16);
            #pragma unroll
            for (int i = 0; i < 4; i++)
                *(uint2*)(sm + S_A0 + (uint)grow * E_AW + 256 + i * 8) = f4h(ep[i]);
        }
        if (tid < 64) ((int*)(sm + S_DST))[tid] = dst[t * 64 + tid];
    }
    __syncthreads();

    int cur = 0;
    for (; t < ntiles; t += step) {
        const int tn = t + step;
        const bool pfv = (tn < ntiles);
        char* aBuf = sm + (cur ? S_A1 : S_A0);
        char* nBuf = sm + (cur ? S_A0 : S_A1);
        const uint32_t aB = base + (cur ? S_A1 : S_A0);
        const int* sDstC = (const int*)(sm + S_DST) + cur * 64;
        int* sDstN = (int*)(sm + S_DST) + (cur ^ 1) * 64;

        // ---- prefetch issue #1: first half of h rows + ea + dst ----
        const float4* hpn = 0;
        float4 pf[4], pe[4];
        int pd = 0;
        if (pfv) {
            const int e = tn * 64 + grow;
            const int s = src[e];
            hpn = (const float4*)(g_h + (size_t)s * 128) + gq * 8;
            #pragma unroll
            for (int i = 0; i < 4; i++) pf[i] = hpn[i];
            if (gq == 0) {
                const float4* ep = (const float4*)(edge_attr + (size_t)e * 16);
                #pragma unroll
                for (int i = 0; i < 4; i++) pe[i] = ep[i];
            }
            if (tid < 64) pd = dst[tn * 64 + tid];
        }

        // ---- GEMM1 (K=144, 2-pass weight split) ----
        float acc[8][4];
        #pragma unroll
        for (int i = 0; i < 8; i++) { acc[i][0]=0; acc[i][1]=0; acc[i][2]=0; acc[i][3]=0; }
        wgemm2<9, 4, E_AW>(&acc[0][0], aB, w1H, w1L, aOff, bOff);
        __syncthreads();   // all warps done reading A before Hid overwrite

        // ---- epilogue1: relu(+b1) -> fp16 into cur buf ----
        #pragma unroll
        for (int mt = 0; mt < 2; mt++)
            #pragma unroll
            for (int nt = 0; nt < 4; nt++) {
                float* a4 = acc[mt * 4 + nt];
                const int col = n0 + nt * 8 + 2 * q;
                const int r0 = m0 + mt * 16 + (lane >> 2);
                float v0 = fmaxf(a4[0] + sb1[col], 0.f), v1 = fmaxf(a4[1] + sb1[col+1], 0.f);
                float v2 = fmaxf(a4[2] + sb1[col], 0.f), v3 = fmaxf(a4[3] + sb1[col+1], 0.f);
                *(uint*)(aBuf + (uint)r0 * E_AW + col * 2) = h2w(v0, v1);
                *(uint*)(aBuf + (uint)(r0 + 8) * E_AW + col * 2) = h2w(v2, v3);
            }

        // ---- drain prefetch #1 into next buf; issue prefetch #2 ----
        if (pfv) {
            #pragma unroll
            for (int i = 0; i < 4; i++)
                *(uint2*)(nBuf + gb0 + i * 8) = f4h(pf[i]);
            if (gq == 0) {
                #pragma unroll
                for (int i = 0; i < 4; i++)
                    *(uint2*)(nBuf + (uint)grow * E_AW + 256 + i * 8) = f4h(pe[i]);
            }
            if (tid < 64) sDstN[tid] = pd;
            #pragma unroll
            for (int i = 0; i < 4; i++) pf[i] = hpn[4 + i];
        }
        __syncthreads();   // Hid visible to all warps

        // ---- GEMM2 (K=128, 2-pass weight split) ----
        #pragma unroll
        for (int i = 0; i < 8; i++) { acc[i][0]=0; acc[i][1]=0; acc[i][2]=0; acc[i][3]=0; }
        wgemm2<8, 4, E_AW>(&acc[0][0], aB, w2H, w2L, aOff, bOff);

        // ---- epilogue2: +b2, lane-pair shuffle -> one v4 reduction each ----
        #pragma unroll
        for (int mt = 0; mt < 2; mt++)
            #pragma unroll
            for (int nt = 0; nt < 4; nt++) {
                float* a4 = acc[mt * 4 + nt];
                const int col  = n0 + nt * 8 + 2 * q;
                const int colb = n0 + nt * 8 + 2 * (q & ~1);
                const int r0 = m0 + mt * 16 + (lane >> 2);
                const float v0 = a4[0] + sb2[col], v1 = a4[1] + sb2[col + 1];
                const float v2 = a4[2] + sb2[col], v3 = a4[3] + sb2[col + 1];
                const float s0 = qodd ? v0 : v2;
                const float s1 = qodd ? v1 : v3;
                const float x0 = __shfl_xor_sync(0xffffffffu, s0, 1);
                const float x1 = __shfl_xor_sync(0xffffffffu, s1, 1);
                const int drow = qodd ? sDstC[r0 + 8] : sDstC[r0];
                float* p = g_agg + (size_t)drow * 128 + colb;
                if (qodd) red_add_v4(p, x0, x1, v2, v3);
                else      red_add_v4(p, v0, v1, x0, x1);
            }

        // ---- drain prefetch #2 into next buf ----
        if (pfv) {
            #pragma unroll
            for (int i = 0; i < 4; i++)
                *(uint2*)(nBuf + gb0 + 32 + i * 8) = f4h(pf[i]);
        }
        __syncthreads();   // next buf complete before next iteration's GEMM1
        cur ^= 1;
    }
}

// ============================================================================
// node GEMM body (mma): out[n,128] = act(A[n,128] @ W + b); 64-row tiles,
// 256 thr = 8 warps (warp 32x32), 2 CTAs/SM. Weights fp16 hi/lo 2-pass.
// ============================================================================
#define N_AW 272                 // A stride bytes (136 halves)
#define NS_WH 0
#define NS_WL 34816
#define NS_A  69632
#define NS_B  87040
#define NODE_SMEM 87552

__device__ __forceinline__ void node_body(
    const float* __restrict__ A, float* __restrict__ out, int ostride,
    const uint* __restrict__ WhU, const uint* __restrict__ WlU,
    const float* __restrict__ bias, int relu)
{
    extern __shared__ char sm[];
    const int tid = threadIdx.x;
    const int wid = tid >> 5, lane = tid & 31;
    const uint32_t base = sm_addr(sm);

    for (int i = tid; i < 128 * 64; i += 256) {
        const int k = i >> 6, n2 = i & 63;
        ((uint*)(sm + NS_WH))[k * 68 + n2] = WhU[i];
        ((uint*)(sm + NS_WL))[k * 68 + n2] = WlU[i];
    }
    if (tid < 128) ((float*)(sm + NS_B))[tid] = bias[tid];
    __syncthreads();

    const float* sb = (const float*)(sm + NS_B);
    const int m0 = (wid & 1) * 32, n0 = (wid >> 1) * 32;
    const uint32_t aOff = (uint32_t)(m0 + (lane & 15)) * N_AW + (lane >> 4) * 16;
    const uint32_t bOff = (uint32_t)(lane & 15) * 272 + n0 * 2 + (lane >> 4) * 16;
    const uint32_t aB = base + NS_A;
    const uint32_t wH = base + NS_WH, wL = base + NS_WL;

    const int ntiles = (N_NODES + 63) / 64;  // 782
    for (int t = blockIdx.x; t < ntiles; t += gridDim.x) {
        const int r0g = t * 64;
        {   // load + convert A rows
            const int trow = tid >> 2, qq = tid & 3;
            const int rg = r0g + trow;
            const uint b0 = (uint)trow * N_AW + qq * 64;
            if (rg < N_NODES) {
                const float4* hp = (const float4*)(A + (size_t)rg * 128) + qq * 8;
                #pragma unroll
                for (int i = 0; i < 8; i++)
                    *(uint2*)(sm + NS_A + b0 + i * 8) = f4h(hp[i]);
            } else {
                const uint2 z = make_uint2(0u, 0u);
                #pragma unroll
                for (int i = 0; i < 8; i++)
                    *(uint2*)(sm + NS_A + b0 + i * 8) = z;
            }
        }
        __syncthreads();

        float acc[8][4];
        #pragma unroll
        for (int i = 0; i < 8; i++) { acc[i][0]=0; acc[i][1]=0; acc[i][2]=0; acc[i][3]=0; }
        wgemm2<8, 4, N_AW>(&acc[0][0], aB, wH, wL, aOff, bOff);
        __syncthreads();

        #pragma unroll
        for (int mt = 0; mt < 2; mt++)
            #pragma unroll
            for (int nt = 0; nt < 4; nt++) {
                float* a4 = acc[mt * 4 + nt];
                const int col = n0 + nt * 8 + 2 * (lane & 3);
                const int r = m0 + mt * 16 + (lane >> 2);
                const int rg0 = r0g + r, rg1 = rg0 + 8;
                float v0 = a4[0] + sb[col], v1 = a4[1] + sb[col + 1];
                float v2 = a4[2] + sb[col], v3 = a4[3] + sb[col + 1];
                if (relu) {
                    v0 = fmaxf(v0, 0.f); v1 = fmaxf(v1, 0.f);
                    v2 = fmaxf(v2, 0.f); v3 = fmaxf(v3, 0.f);
                }
                if (rg0 < N_NODES)
                    *(float2*)(out + (size_t)rg0 * ostride + col) = make_float2(v0, v1);
                if (rg1 < N_NODES)
                    *(float2*)(out + (size_t)rg1 * ostride + col) = make_float2(v2, v3);
            }
    }
}

__global__ __launch_bounds__(256, 2) void lin_mma_kernel(
    const float* __restrict__ x, const float* __restrict__ b)
{
    node_body(x, g_h, 128, (const uint*)(g_wh + OFF_LIN),
              (const uint*)(g_wl + OFF_LIN), b, 1);
}

__global__ __launch_bounds__(256, 2) void gru_mma_kernel(
    int l, const float* __restrict__ bih, const float* __restrict__ bhh)
{
    const int which = blockIdx.y / 3, gate = blockIdx.y % 3;
    const float* A = which ? g_h : g_agg;
    float* out = (which ? g_gh : g_gi) + gate * 128;
    const size_t wOff = (size_t)(which ? OFF_WHH : OFF_WIH) + (size_t)(l * 3 + gate) * 16384;
    const float* bias = (which ? bhh : bih) + gate * 128;
    node_body(A, out, 384, (const uint*)(g_wh + wOff), (const uint*)(g_wl + wOff), bias, 0);
}

// ============================================================================
// fused GRU gates + BatchNorm + residual
// ============================================================================
__global__ void gru_gate_kernel(
    const float* __restrict__ gamma, const float* __restrict__ beta,
    const float* __restrict__ mean, const float* __restrict__ var)
{
    const int idx = blockIdx.x * blockDim.x + threadIdx.x;
    if (idx >= N_NODES * HIDDEN) return;
    const int c = idx & 127;
    const size_t n = (size_t)(idx >> 7);
    const float* gi = g_gi + n * 384;
    const float* gh = g_gh + n * 384;
    const float hv = g_h[idx];
    const float r = 1.f / (1.f + expf(-(gi[c] + gh[c])));
    const float z = 1.f / (1.f + expf(-(gi[128 + c] + gh[128 + c])));
    const float nn = tanhf(gi[256 + c] + r * gh[256 + c]);
    const float hnew = (1.f - z) * nn + z * hv;
    const float bn = (hnew - mean[c]) * rsqrtf(var[c] + 1e-5f) * gamma[c] + beta[c];
    g_h[idx] = hv + bn;
}

// ---------------- aux kernels ----------------
__global__ void zero_agg_kernel() {
    const int idx = blockIdx.x * blockDim.x + threadIdx.x;
    if (idx < N_NODES * HIDDEN / 4)
        ((float4*)g_agg)[idx] = make_float4(0.f, 0.f, 0.f, 0.f);
}

__global__ void init_readout_kernel() {
    const int idx = blockIdx.x * blockDim.x + threadIdx.x;
    if (idx < N_GRAPHS * HIDDEN) { g_zsum[idx] = 0.f; g_zmax[idx] = 0x00800000u; }
    if (idx < N_GRAPHS) g_cnt[idx] = 0.f;
}

__global__ void seg_reduce_kernel(const int* __restrict__ batch) {
    const int gid = blockIdx.x * blockDim.x + threadIdx.x;
    if (gid >= N_NODES * 32) return;
    const int n = gid >> 5, q = gid & 31;
    const int g = batch[n];
    const float4 hv = *(const float4*)(g_h + (size_t)n * 128 + q * 4);
    red_add_v4(g_zsum + g * 128 + q * 4, hv.x, hv.y, hv.z, hv.w);
    unsigned* zm = g_zmax + g * 128 + q * 4;
    atomicMax(zm + 0, fenc(hv.x)); atomicMax(zm + 1, fenc(hv.y));
    atomicMax(zm + 2, fenc(hv.z)); atomicMax(zm + 3, fenc(hv.w));
    if (q == 0) atomicAdd(g_cnt + g, 1.f);
}

__global__ void readout_kernel(const float* __restrict__ ro_w,
                               const float* __restrict__ ro_b,
                               float* __restrict__ out)
{
    __shared__ float sbuf[256];
    const int g = blockIdx.x, j = threadIdx.x;
    const float c = g_cnt[g];
    const float inv = 1.f / fmaxf(c, 1.f);
    sbuf[j]       = g_zsum[g * 128 + j] * inv;
    sbuf[128 + j] = (c > 0.f) ? fdec(g_zmax[g * 128 + j]) : 0.f;
    __syncthreads();
    float acc = ro_b[j];
    #pragma unroll 8
    for (int k = 0; k < 256; k++) acc = fmaf(sbuf[k], ro_w[k * 128 + j], acc);
    out[g * 128 + j] = fmaxf(acc, 0.f);
}

// ============================================================================
extern "C" void kernel_launch(void* const* d_in, const int* in_sizes, int n_in,
                              void* d_out, int out_size)
{
    const int shift = (in_sizes[4] == 1) ? 1 : 0;
    const float* x         = (const float*)d_in[0];
    const int*   edge_idx  = (const int*)  d_in[1];
    const float* edge_attr = (const float*)d_in[2];
    const int*   batch     = (const int*)  d_in[3];
    const float* lin_in_w  = (const float*)d_in[4 + shift];
    const float* lin_in_b  = (const float*)d_in[5 + shift];
    const float* msg_w1    = (const float*)d_in[6 + shift];
    const float* msg_b1    = (const float*)d_in[7 + shift];
    const float* msg_w2    = (const float*)d_in[8 + shift];
    const float* msg_b2    = (const float*)d_in[9 + shift];
    const float* bn_gamma  = (const float*)d_in[10 + shift];
    const float* bn_beta   = (const float*)d_in[11 + shift];
    const float* bn_mean   = (const float*)d_in[12 + shift];
    const float* bn_var    = (const float*)d_in[13 + shift];
    const float* gru_wih   = (const float*)d_in[14 + shift];
    const float* gru_whh   = (const float*)d_in[15 + shift];
    const float* gru_bih   = (const float*)d_in[16 + shift];
    const float* gru_bhh   = (const float*)d_in[17 + shift];
    const float* ro_w      = (const float*)d_in[18 + shift];
    const float* ro_b      = (const float*)d_in[19 + shift];
    float* out = (float*)d_out;

    static bool inited = false;
    if (!inited) {
        cudaFuncSetAttribute(edge_mma_kernel, cudaFuncAttributeMaxDynamicSharedMemorySize, EDGE_SMEM);
        cudaFuncSetAttribute(lin_mma_kernel,  cudaFuncAttributeMaxDynamicSharedMemorySize, NODE_SMEM);
        cudaFuncSetAttribute(gru_mma_kernel,  cudaFuncAttributeMaxDynamicSharedMemorySize, NODE_SMEM);
        inited = true;
    }

    const int* src = edge_idx;
    const int* dst = edge_idx + N_EDGES;

    conv_w_kernel<<<dim3(576, 5), 256>>>(lin_in_w, msg_w1, msg_w2, gru_wih, gru_whh);
    lin_mma_kernel<<<296, 256, NODE_SMEM>>>(x, lin_in_b);

    for (int l = 0; l < N_LAYERS; l++) {
        zero_agg_kernel<<<(N_NODES * HIDDEN / 4 + 255) / 256, 256>>>();
        edge_mma_kernel<<<148, 256, EDGE_SMEM>>>(
            src, dst, edge_attr, l, msg_b1 + l * 128, msg_b2 + l * 128);
        gru_mma_kernel<<<dim3(296, 6), 256, NODE_SMEM>>>(
            l, gru_bih + (size_t)l * 384, gru_bhh + (size_t)l * 384);
        gru_gate_kernel<<<(N_NODES * HIDDEN + 255) / 256, 256>>>(
            bn_gamma + l * 128, bn_beta + l * 128, bn_mean + l * 128, bn_var + l * 128);
    }

    init_readout_kernel<<<(N_GRAPHS * HIDDEN + 255) / 256, 256>>>();
    seg_reduce_kernel<<<(N_NODES * 32 + 255) / 256, 256>>>(batch);
    readout_kernel<<<N_GRAPHS, 128>>>(ro_w, ro_b, out);
}